// round 5
// baseline (speedup 1.0000x reference)
#include <cuda_runtime.h>

// Problem constants
#define NN    2048          // meta nodes
#define MDIM  64            // subgraph nodes
#define DDIM  64            // channels
#define FDIM  4096          // MDIM*DDIM
#define OUTD  64
#define LN_EPS 1e-5f

// ------------------------- scratch (device globals; no allocation) ----------
__device__ float g_Af[NN * NN];
__device__ float g_A2[NN * NN];
__device__ float g_A3[NN * NN];
__device__ float g_X [NN * FDIM];
__device__ float g_B1[NN * FDIM];
__device__ float g_B2[NN * FDIM];
__device__ float g_Y [NN * FDIM];
__device__ float g_Sn[MDIM * MDIM];

// ------------------------- int32 -> float cast ------------------------------
__global__ void cast_i2f(const int* __restrict__ a, float* __restrict__ o) {
    int i = blockIdx.x * blockDim.x + threadIdx.x;
    o[i] = (float)a[i];
}

// ------------------------- Sn = D^-1/2 (S+I) D^-1/2 -------------------------
__global__ void compute_sn(const int* __restrict__ sub_adj, float* __restrict__ Sn) {
    __shared__ float dinv[MDIM];
    int u = threadIdx.x;                 // 64 threads
    float s = 1.0f;                      // self loop
    for (int v = 0; v < MDIM; v++) s += (float)sub_adj[u * MDIM + v];
    dinv[u] = rsqrtf(s);
    __syncthreads();
    float du = dinv[u];
    for (int v = 0; v < MDIM; v++) {
        float a = (float)sub_adj[u * MDIM + v] + (u == v ? 1.0f : 0.0f);
        Sn[u * MDIM + v] = du * a * dinv[v];
    }
}

// ------------------------- big SGEMM: C = A(MxK) * B(KxN) -------------------
// All dims multiples of tile sizes. 128x128x8, 256 threads, 8x8 per thread.
#define BM 128
#define BN 128
#define BK 8

__global__ __launch_bounds__(256, 2)
void sgemm128(const float* __restrict__ A, const float* __restrict__ B,
              float* __restrict__ C, int M, int N, int K) {
    __shared__ float As[BK][BM];
    __shared__ float Bs[BK][BN];

    const int bm = blockIdx.y * BM;
    const int bn = blockIdx.x * BN;
    const int t  = threadIdx.x;
    const int w    = t >> 5;
    const int lane = t & 31;
    // 8 warps: 4x2 warp grid, each warp 32 rows x 64 cols
    const int wr = w >> 1, wc = w & 1;
    const int lr = lane >> 3, lc = lane & 7;
    const int row0 = wr * 32 + lr * 8;
    const int col0 = wc * 64 + lc * 8;

    // load mapping
    const int arow = t >> 1;            // 0..127
    const int ac4  = (t & 1) * 4;       // 0 or 4
    const int brow = t >> 5;            // 0..7
    const int bc4  = (t & 31) * 4;      // 0..124

    const float* Aptr = A + (long)(bm + arow) * K + ac4;
    const float* Bptr = B + (long)brow * N + bn + bc4;

    float acc[8][8];
    #pragma unroll
    for (int i = 0; i < 8; i++)
        #pragma unroll
        for (int j = 0; j < 8; j++) acc[i][j] = 0.0f;

    float4 av = *(const float4*)(Aptr);
    float4 bv = *(const float4*)(Bptr);

    for (int k0 = 0; k0 < K; k0 += BK) {
        As[ac4 + 0][arow] = av.x;
        As[ac4 + 1][arow] = av.y;
        As[ac4 + 2][arow] = av.z;
        As[ac4 + 3][arow] = av.w;
        *(float4*)&Bs[brow][bc4] = bv;
        __syncthreads();

        if (k0 + BK < K) {                      // register prefetch of next tile
            av = *(const float4*)(Aptr + (k0 + BK));
            bv = *(const float4*)(Bptr + (long)(k0 + BK) * N);
        }

        #pragma unroll
        for (int kk = 0; kk < BK; kk++) {
            float a[8], b[8];
            *(float4*)(a)     = *(const float4*)&As[kk][row0];
            *(float4*)(a + 4) = *(const float4*)&As[kk][row0 + 4];
            *(float4*)(b)     = *(const float4*)&Bs[kk][col0];
            *(float4*)(b + 4) = *(const float4*)&Bs[kk][col0 + 4];
            #pragma unroll
            for (int i = 0; i < 8; i++)
                #pragma unroll
                for (int j = 0; j < 8; j++)
                    acc[i][j] += a[i] * b[j];
        }
        __syncthreads();
    }

    #pragma unroll
    for (int i = 0; i < 8; i++) {
        float4 v0 = make_float4(acc[i][0], acc[i][1], acc[i][2], acc[i][3]);
        float4 v1 = make_float4(acc[i][4], acc[i][5], acc[i][6], acc[i][7]);
        float* Cp = C + (long)(bm + row0 + i) * N + bn + col0;
        *(float4*)(Cp)     = v0;
        *(float4*)(Cp + 4) = v1;
    }
}

// ------------------- weight apply: Y(R,64) (+)= X(R,64) @ W(64,64) ----------
// grid: R/64 blocks, 256 threads
__global__ __launch_bounds__(256)
void wgemm64(const float* __restrict__ X, const float* __restrict__ W,
             float* __restrict__ Y, int accumulate) {
    __shared__ float Xs[64][68];
    __shared__ float Ws[64][64];
    const int t = threadIdx.x;
    const long row0 = (long)blockIdx.x * 64;

    #pragma unroll
    for (int i = 0; i < 16; i++) {
        int idx = t + i * 256;
        ((float*)Ws)[idx] = W[idx];
        int r = idx >> 6, c = idx & 63;
        Xs[r][c] = X[(row0 + r) * 64 + c];
    }
    __syncthreads();

    const int r  = t >> 2;
    const int c0 = (t & 3) * 16;
    float acc[16];
    if (accumulate) {
        #pragma unroll
        for (int q = 0; q < 4; q++)
            *(float4*)&acc[q * 4] = *(const float4*)(Y + (row0 + r) * 64 + c0 + q * 4);
    } else {
        #pragma unroll
        for (int j = 0; j < 16; j++) acc[j] = 0.0f;
    }
    #pragma unroll 8
    for (int d = 0; d < 64; d++) {
        float xv = Xs[r][d];
        #pragma unroll
        for (int j = 0; j < 16; j++) acc[j] += xv * Ws[d][c0 + j];
    }
    #pragma unroll
    for (int q = 0; q < 4; q++)
        *(float4*)(Y + (row0 + r) * 64 + c0 + q * 4) = *(float4*)&acc[q * 4];
}

// -------- per-n: H = Sn @ Y[n] + bias_sum ; LayerNorm(m,d) ; ReLU -> X ------
__global__ __launch_bounds__(256)
void sn_ln_relu(const float* __restrict__ Y, const float* __restrict__ Sn,
                const float* __restrict__ bconv_l,   // (4,64)
                const float* __restrict__ gamma_l,   // (64,64)
                const float* __restrict__ beta_l,    // (64,64)
                float* __restrict__ Xout) {
    __shared__ float Ys[64][68];
    __shared__ float Sns[64][68];
    __shared__ float red[8];
    __shared__ float s_mu, s_rstd;

    const int n = blockIdx.x;
    const int t = threadIdx.x;
    const float* Yn = Y + (long)n * FDIM;

    #pragma unroll
    for (int i = 0; i < 16; i++) {
        int idx = t + i * 256;
        int r = idx >> 6, c = idx & 63;
        Ys[r][c]  = Yn[idx];
        Sns[r][c] = Sn[idx];
    }
    __syncthreads();

    const int u  = t >> 2;
    const int c0 = (t & 3) * 16;

    float h[16];
    #pragma unroll
    for (int j = 0; j < 16; j++)
        h[j] = bconv_l[c0 + j] + bconv_l[64 + c0 + j] +
               bconv_l[128 + c0 + j] + bconv_l[192 + c0 + j];

    #pragma unroll 8
    for (int v = 0; v < 64; v++) {
        float s = Sns[u][v];
        #pragma unroll
        for (int j = 0; j < 16; j++) h[j] += s * Ys[v][c0 + j];
    }

    // block mean
    const int lane = t & 31, wid = t >> 5;
    float lsum = 0.0f;
    #pragma unroll
    for (int j = 0; j < 16; j++) lsum += h[j];
    #pragma unroll
    for (int o = 16; o > 0; o >>= 1) lsum += __shfl_xor_sync(0xffffffffu, lsum, o);
    if (lane == 0) red[wid] = lsum;
    __syncthreads();
    if (t == 0) {
        float s = 0.0f;
        #pragma unroll
        for (int i = 0; i < 8; i++) s += red[i];
        s_mu = s * (1.0f / 4096.0f);
    }
    __syncthreads();
    const float mu = s_mu;

    // block variance (two-pass, matches jnp.var)
    float lv = 0.0f;
    #pragma unroll
    for (int j = 0; j < 16; j++) { float d = h[j] - mu; lv += d * d; }
    #pragma unroll
    for (int o = 16; o > 0; o >>= 1) lv += __shfl_xor_sync(0xffffffffu, lv, o);
    if (lane == 0) red[wid] = lv;
    __syncthreads();
    if (t == 0) {
        float s = 0.0f;
        #pragma unroll
        for (int i = 0; i < 8; i++) s += red[i];
        s_rstd = rsqrtf(s * (1.0f / 4096.0f) + LN_EPS);
    }
    __syncthreads();
    const float rstd = s_rstd;

    float* Xn = Xout + (long)n * FDIM + u * 64 + c0;
    const float* gp = gamma_l + u * 64 + c0;
    const float* bp = beta_l  + u * 64 + c0;
    #pragma unroll
    for (int j = 0; j < 16; j++) {
        float v = (h[j] - mu) * rstd * gp[j] + bp[j];
        Xn[j] = fmaxf(v, 0.0f);
    }
}

// ----------- readout: out(2048,64) = X(2048,4096) @ Wl(4096,64) + bl --------
// grid: 2048/16 = 128 blocks, 256 threads
__global__ __launch_bounds__(256)
void final_gemm(const float* __restrict__ X, const float* __restrict__ Wl,
                const float* __restrict__ bl, float* __restrict__ out) {
    __shared__ float Xs[16][128];
    __shared__ float Ws[128][68];
    const int t = threadIdx.x;
    const long m0 = (long)blockIdx.x * 16;
    const int r  = t >> 4;          // 0..15
    const int cq = (t & 15) * 4;    // 0..60

    float acc[4] = {0.f, 0.f, 0.f, 0.f};

    for (int k0 = 0; k0 < FDIM; k0 += 128) {
        #pragma unroll
        for (int i = 0; i < 2; i++) {
            int idx = t + i * 256;              // float4 idx 0..511
            int rr = idx >> 5, cc = (idx & 31) * 4;
            *(float4*)&Xs[rr][cc] = *(const float4*)(X + (m0 + rr) * FDIM + k0 + cc);
        }
        #pragma unroll
        for (int i = 0; i < 8; i++) {
            int idx = t + i * 256;              // float4 idx 0..2047
            int kk = idx >> 4, cc = (idx & 15) * 4;
            float4 v = *(const float4*)(Wl + (long)(k0 + kk) * 64 + cc);
            Ws[kk][cc] = v.x; Ws[kk][cc + 1] = v.y; Ws[kk][cc + 2] = v.z; Ws[kk][cc + 3] = v.w;
        }
        __syncthreads();
        #pragma unroll 16
        for (int kk = 0; kk < 128; kk++) {
            float xv = Xs[r][kk];
            #pragma unroll
            for (int j = 0; j < 4; j++) acc[j] += xv * Ws[kk][cq + j];
        }
        __syncthreads();
    }
    float4 v = make_float4(acc[0] + bl[cq], acc[1] + bl[cq + 1],
                           acc[2] + bl[cq + 2], acc[3] + bl[cq + 3]);
    *(float4*)(out + (m0 + r) * 64 + cq) = v;
}

// ---------------------------------------------------------------------------
extern "C" void kernel_launch(void* const* d_in, const int* in_sizes, int n_in,
                              void* d_out, int out_size) {
    const float* x_in    = (const float*)d_in[0];   // (2048,64,64)
    const int*   sub_adj = (const int*)  d_in[1];   // (64,64)
    const int*   adj     = (const int*)  d_in[2];   // (2048,2048)
    const float* W_convs = (const float*)d_in[3];   // (3,4,64,64)
    const float* b_convs = (const float*)d_in[4];   // (3,4,64)
    const float* ln_g    = (const float*)d_in[5];   // (3,64,64)
    const float* ln_b    = (const float*)d_in[6];   // (3,64,64)
    const float* W_lin   = (const float*)d_in[7];   // (4096,64)
    const float* b_lin   = (const float*)d_in[8];   // (64)
    float* out = (float*)d_out;

    float *Af, *A2, *A3, *X, *B1, *B2, *Y, *Sn;
    cudaGetSymbolAddress((void**)&Af, g_Af);
    cudaGetSymbolAddress((void**)&A2, g_A2);
    cudaGetSymbolAddress((void**)&A3, g_A3);
    cudaGetSymbolAddress((void**)&X,  g_X);
    cudaGetSymbolAddress((void**)&B1, g_B1);
    cudaGetSymbolAddress((void**)&B2, g_B2);
    cudaGetSymbolAddress((void**)&Y,  g_Y);
    cudaGetSymbolAddress((void**)&Sn, g_Sn);

    // precompute: A as float, A^2, A^3, Sn
    cast_i2f<<<(NN * NN) / 256, 256>>>(adj, Af);
    sgemm128<<<dim3(NN / BN, NN / BM), 256>>>(Af, Af, A2, NN, NN, NN);
    sgemm128<<<dim3(NN / BN, NN / BM), 256>>>(A2, Af, A3, NN, NN, NN);
    compute_sn<<<1, 64>>>(sub_adj, Sn);

    const int RB = (NN * MDIM) / 64;   // wgemm blocks = 2048
    for (int l = 0; l < 3; l++) {
        const float* curX = (l == 0) ? x_in : X;
        const float* Wl = W_convs + (long)l * 4 * 4096;

        // Y = curX @ W0
        wgemm64<<<RB, 256>>>(curX, Wl + 0 * 4096, Y, 0);
        // x1 = A @ x ; Y += x1 @ W1
        sgemm128<<<dim3(FDIM / BN, NN / BM), 256>>>(Af, curX, B1, NN, FDIM, NN);
        wgemm64<<<RB, 256>>>(B1, Wl + 1 * 4096, Y, 1);
        // x2 = A^2 @ x1 ; Y += x2 @ W2
        sgemm128<<<dim3(FDIM / BN, NN / BM), 256>>>(A2, B1, B2, NN, FDIM, NN);
        wgemm64<<<RB, 256>>>(B2, Wl + 2 * 4096, Y, 1);
        // x3 = A^3 @ x2 ; Y += x3 @ W3
        sgemm128<<<dim3(FDIM / BN, NN / BM), 256>>>(A3, B2, B1, NN, FDIM, NN);
        wgemm64<<<RB, 256>>>(B1, Wl + 3 * 4096, Y, 1);

        // X = relu(LN(Sn @ Y + sum_i b_i))
        sn_ln_relu<<<NN, 256>>>(Y, Sn,
                                b_convs + (long)l * 256,
                                ln_g + (long)l * 4096,
                                ln_b + (long)l * 4096,
                                X);
    }

    final_gemm<<<NN / 16, 256>>>(X, W_lin, b_lin, out);
}

// round 6
// speedup vs baseline: 1.8350x; 1.8350x over previous
#include <cuda_runtime.h>
#include <cstdint>

// Problem constants
#define NN    2048          // meta nodes
#define MDIM  64            // subgraph nodes
#define DDIM  64            // channels
#define FDIM  4096          // MDIM*DDIM
#define OUTD  64
#define LN_EPS 1e-5f

// ------------------------- scratch (device globals; no allocation) ----------
__device__ float g_Af[NN * NN];
__device__ float g_A2[NN * NN];
__device__ float g_A3[NN * NN];
__device__ float g_X [NN * FDIM];
__device__ float g_B1[NN * FDIM];
__device__ float g_B2[NN * FDIM];
__device__ float g_Y [NN * FDIM];
__device__ float g_Sn[MDIM * MDIM];

// ------------------------- int32 -> float cast ------------------------------
__global__ void cast_i2f(const int* __restrict__ a, float* __restrict__ o) {
    int i = blockIdx.x * blockDim.x + threadIdx.x;
    o[i] = (float)a[i];
}

// ------------------------- Sn = D^-1/2 (S+I) D^-1/2 -------------------------
__global__ void compute_sn(const int* __restrict__ sub_adj, float* __restrict__ Sn) {
    __shared__ float dinv[MDIM];
    int u = threadIdx.x;                 // 64 threads
    float s = 1.0f;                      // self loop
    for (int v = 0; v < MDIM; v++) s += (float)sub_adj[u * MDIM + v];
    dinv[u] = rsqrtf(s);
    __syncthreads();
    float du = dinv[u];
    for (int v = 0; v < MDIM; v++) {
        float a = (float)sub_adj[u * MDIM + v] + (u == v ? 1.0f : 0.0f);
        Sn[u * MDIM + v] = du * a * dinv[v];
    }
}

// ------------------------- tf32 helpers --------------------------------------
__device__ __forceinline__ float to_tf32(float x) {
    uint32_t u;
    asm("cvt.rna.tf32.f32 %0, %1;" : "=r"(u) : "f"(x));
    return __uint_as_float(u);
}

__device__ __forceinline__ void mma_tf32(float c[4], const uint32_t a[4],
                                         const uint32_t b[2]) {
    asm volatile(
        "mma.sync.aligned.m16n8k8.row.col.f32.tf32.tf32.f32 "
        "{%0,%1,%2,%3}, {%4,%5,%6,%7}, {%8,%9}, {%0,%1,%2,%3};\n"
        : "+f"(c[0]), "+f"(c[1]), "+f"(c[2]), "+f"(c[3])
        : "r"(a[0]), "r"(a[1]), "r"(a[2]), "r"(a[3]), "r"(b[0]), "r"(b[1]));
}

// ------------------------- tensor-core GEMM: C = A(MxK) * B(KxN) ------------
// fp32 in/out, tf32 mma. Block 128x128x32, 256 threads, warp tile 64x32.
// As stored [k][m] (transposed) with pad 136 + XOR-16 swizzle on m by bit4 of k:
// coalesced global A loads, conflict-free STS and frag LDS.
#define TBK 32
#define SPAD 136

__global__ __launch_bounds__(256, 1)
void gemm_tf32(const float* __restrict__ A, const float* __restrict__ B,
               float* __restrict__ C, int M, int N, int K) {
    __shared__ float As[TBK][SPAD];
    __shared__ float Bs[TBK][SPAD];

    const int t  = threadIdx.x;
    const int bm = blockIdx.y * 128;
    const int bn = blockIdx.x * 128;
    const int lane = t & 31;
    const int g  = lane >> 2;           // 0..7
    const int tg = lane & 3;            // 0..3
    const int w  = t >> 5;
    const int wm = (w >> 2) * 64;       // 0 or 64
    const int wn = (w & 3) * 32;        // 0,32,64,96

    // A global load: row = t>>1, k-half = 16*(t&1). Coalesced (2 lanes per row).
    const int am   = t >> 1;            // 0..127
    const int asel = t & 1;             // selects k 0..15 or 16..31
    const int amc  = am ^ (asel << 4);  // swizzled smem column
    const float* Ap = A + (long)(bm + am) * K + asel * 16;

    // B global load: k-row = t>>5, n4 = (t&31)*4. Coalesced.
    const int bk  = t >> 5;             // 0..7
    const int bnc = (t & 31) * 4;
    const float* Bp = B + (long)bk * N + bn + bnc;

    float4 va[4], vb[4];
    #pragma unroll
    for (int i = 0; i < 4; i++) {
        va[i] = *(const float4*)(Ap + 4 * i);
        vb[i] = *(const float4*)(Bp + (long)(8 * i) * N);
    }

    float c[4][4][4];
    #pragma unroll
    for (int im = 0; im < 4; im++)
        #pragma unroll
        for (int in = 0; in < 4; in++) {
            c[im][in][0] = 0.f; c[im][in][1] = 0.f;
            c[im][in][2] = 0.f; c[im][in][3] = 0.f;
        }

    for (int k0 = 0; k0 < K; k0 += TBK) {
        // stage tile into smem, rounding to tf32 once here
        #pragma unroll
        for (int i = 0; i < 4; i++) {
            int kl = asel * 16 + 4 * i;
            As[kl + 0][amc] = to_tf32(va[i].x);
            As[kl + 1][amc] = to_tf32(va[i].y);
            As[kl + 2][amc] = to_tf32(va[i].z);
            As[kl + 3][amc] = to_tf32(va[i].w);
            float4 bv;
            bv.x = to_tf32(vb[i].x); bv.y = to_tf32(vb[i].y);
            bv.z = to_tf32(vb[i].z); bv.w = to_tf32(vb[i].w);
            *(float4*)&Bs[bk + 8 * i][bnc] = bv;
        }
        __syncthreads();

        if (k0 + TBK < K) {             // register prefetch of next tile
            #pragma unroll
            for (int i = 0; i < 4; i++) {
                va[i] = *(const float4*)(Ap + (k0 + TBK) + 4 * i);
                vb[i] = *(const float4*)(Bp + (long)(k0 + TBK + 8 * i) * N);
            }
        }

        #pragma unroll
        for (int ks = 0; ks < 4; ks++) {
            const int kr = ks * 8;
            const int sw = (ks >> 1) << 4;   // == 16 * ((kr+tg)>>4) for all frag rows
            uint32_t af[4][4], bf[4][2];
            #pragma unroll
            for (int im = 0; im < 4; im++) {
                const int m0 = (wm + im * 16 + g) ^ sw;
                const int m8 = (wm + im * 16 + g + 8) ^ sw;
                af[im][0] = __float_as_uint(As[kr + tg    ][m0]);
                af[im][1] = __float_as_uint(As[kr + tg    ][m8]);
                af[im][2] = __float_as_uint(As[kr + tg + 4][m0]);
                af[im][3] = __float_as_uint(As[kr + tg + 4][m8]);
            }
            #pragma unroll
            for (int in = 0; in < 4; in++) {
                const int nb = wn + in * 8 + g;
                bf[in][0] = __float_as_uint(Bs[kr + tg    ][nb]);
                bf[in][1] = __float_as_uint(Bs[kr + tg + 4][nb]);
            }
            #pragma unroll
            for (int im = 0; im < 4; im++)
                #pragma unroll
                for (int in = 0; in < 4; in++)
                    mma_tf32(c[im][in], af[im], bf[in]);
        }
        __syncthreads();
    }

    #pragma unroll
    for (int im = 0; im < 4; im++) {
        const long row = bm + wm + im * 16 + g;
        #pragma unroll
        for (int in = 0; in < 4; in++) {
            const int col = bn + wn + in * 8 + 2 * tg;
            float* Cp = C + row * N + col;
            *(float2*)Cp           = make_float2(c[im][in][0], c[im][in][1]);
            *(float2*)(Cp + 8 * N) = make_float2(c[im][in][2], c[im][in][3]);
        }
    }
}

// ------------------- weight apply: Y(R,64) (+)= X(R,64) @ W(64,64) ----------
// grid: R/64 blocks, 256 threads
__global__ __launch_bounds__(256)
void wgemm64(const float* __restrict__ X, const float* __restrict__ W,
             float* __restrict__ Y, int accumulate) {
    __shared__ float Xs[64][68];
    __shared__ float Ws[64][64];
    const int t = threadIdx.x;
    const long row0 = (long)blockIdx.x * 64;

    #pragma unroll
    for (int i = 0; i < 16; i++) {
        int idx = t + i * 256;
        ((float*)Ws)[idx] = W[idx];
        int r = idx >> 6, c = idx & 63;
        Xs[r][c] = X[(row0 + r) * 64 + c];
    }
    __syncthreads();

    const int r  = t >> 2;
    const int c0 = (t & 3) * 16;
    float acc[16];
    if (accumulate) {
        #pragma unroll
        for (int q = 0; q < 4; q++)
            *(float4*)&acc[q * 4] = *(const float4*)(Y + (row0 + r) * 64 + c0 + q * 4);
    } else {
        #pragma unroll
        for (int j = 0; j < 16; j++) acc[j] = 0.0f;
    }
    #pragma unroll 8
    for (int d = 0; d < 64; d++) {
        float xv = Xs[r][d];
        #pragma unroll
        for (int j = 0; j < 16; j++) acc[j] += xv * Ws[d][c0 + j];
    }
    #pragma unroll
    for (int q = 0; q < 4; q++)
        *(float4*)(Y + (row0 + r) * 64 + c0 + q * 4) = *(float4*)&acc[q * 4];
}

// -------- per-n: H = Sn @ Y[n] + bias_sum ; LayerNorm(m,d) ; ReLU -> X ------
__global__ __launch_bounds__(256)
void sn_ln_relu(const float* __restrict__ Y, const float* __restrict__ Sn,
                const float* __restrict__ bconv_l,   // (4,64)
                const float* __restrict__ gamma_l,   // (64,64)
                const float* __restrict__ beta_l,    // (64,64)
                float* __restrict__ Xout) {
    __shared__ float Ys[64][68];
    __shared__ float Sns[64][68];
    __shared__ float red[8];
    __shared__ float s_mu, s_rstd;

    const int n = blockIdx.x;
    const int t = threadIdx.x;
    const float* Yn = Y + (long)n * FDIM;

    #pragma unroll
    for (int i = 0; i < 16; i++) {
        int idx = t + i * 256;
        int r = idx >> 6, c = idx & 63;
        Ys[r][c]  = Yn[idx];
        Sns[r][c] = Sn[idx];
    }
    __syncthreads();

    const int u  = t >> 2;
    const int c0 = (t & 3) * 16;

    float h[16];
    #pragma unroll
    for (int j = 0; j < 16; j++)
        h[j] = bconv_l[c0 + j] + bconv_l[64 + c0 + j] +
               bconv_l[128 + c0 + j] + bconv_l[192 + c0 + j];

    #pragma unroll 8
    for (int v = 0; v < 64; v++) {
        float s = Sns[u][v];
        #pragma unroll
        for (int j = 0; j < 16; j++) h[j] += s * Ys[v][c0 + j];
    }

    // block mean
    const int lane = t & 31, wid = t >> 5;
    float lsum = 0.0f;
    #pragma unroll
    for (int j = 0; j < 16; j++) lsum += h[j];
    #pragma unroll
    for (int o = 16; o > 0; o >>= 1) lsum += __shfl_xor_sync(0xffffffffu, lsum, o);
    if (lane == 0) red[wid] = lsum;
    __syncthreads();
    if (t == 0) {
        float s = 0.0f;
        #pragma unroll
        for (int i = 0; i < 8; i++) s += red[i];
        s_mu = s * (1.0f / 4096.0f);
    }
    __syncthreads();
    const float mu = s_mu;

    // block variance (two-pass, matches jnp.var)
    float lv = 0.0f;
    #pragma unroll
    for (int j = 0; j < 16; j++) { float d = h[j] - mu; lv += d * d; }
    #pragma unroll
    for (int o = 16; o > 0; o >>= 1) lv += __shfl_xor_sync(0xffffffffu, lv, o);
    if (lane == 0) red[wid] = lv;
    __syncthreads();
    if (t == 0) {
        float s = 0.0f;
        #pragma unroll
        for (int i = 0; i < 8; i++) s += red[i];
        s_rstd = rsqrtf(s * (1.0f / 4096.0f) + LN_EPS);
    }
    __syncthreads();
    const float rstd = s_rstd;

    float* Xn = Xout + (long)n * FDIM + u * 64 + c0;
    const float* gp = gamma_l + u * 64 + c0;
    const float* bp = beta_l  + u * 64 + c0;
    #pragma unroll
    for (int j = 0; j < 16; j++) {
        float v = (h[j] - mu) * rstd * gp[j] + bp[j];
        Xn[j] = fmaxf(v, 0.0f);
    }
}

// ----------- readout: out(2048,64) = X(2048,4096) @ Wl(4096,64) + bl --------
// grid: 2048/16 = 128 blocks, 256 threads
__global__ __launch_bounds__(256)
void final_gemm(const float* __restrict__ X, const float* __restrict__ Wl,
                const float* __restrict__ bl, float* __restrict__ out) {
    __shared__ float Xs[16][128];
    __shared__ float Ws[128][68];
    const int t = threadIdx.x;
    const long m0 = (long)blockIdx.x * 16;
    const int r  = t >> 4;          // 0..15
    const int cq = (t & 15) * 4;    // 0..60

    float acc[4] = {0.f, 0.f, 0.f, 0.f};

    for (int k0 = 0; k0 < FDIM; k0 += 128) {
        #pragma unroll
        for (int i = 0; i < 2; i++) {
            int idx = t + i * 256;              // float4 idx 0..511
            int rr = idx >> 5, cc = (idx & 31) * 4;
            *(float4*)&Xs[rr][cc] = *(const float4*)(X + (m0 + rr) * FDIM + k0 + cc);
        }
        #pragma unroll
        for (int i = 0; i < 8; i++) {
            int idx = t + i * 256;              // float4 idx 0..2047
            int kk = idx >> 4, cc = (idx & 15) * 4;
            float4 v = *(const float4*)(Wl + (long)(k0 + kk) * 64 + cc);
            Ws[kk][cc] = v.x; Ws[kk][cc + 1] = v.y; Ws[kk][cc + 2] = v.z; Ws[kk][cc + 3] = v.w;
        }
        __syncthreads();
        #pragma unroll 16
        for (int kk = 0; kk < 128; kk++) {
            float xv = Xs[r][kk];
            #pragma unroll
            for (int j = 0; j < 4; j++) acc[j] += xv * Ws[kk][cq + j];
        }
        __syncthreads();
    }
    float4 v = make_float4(acc[0] + bl[cq], acc[1] + bl[cq + 1],
                           acc[2] + bl[cq + 2], acc[3] + bl[cq + 3]);
    *(float4*)(out + (m0 + r) * 64 + cq) = v;
}

// ---------------------------------------------------------------------------
extern "C" void kernel_launch(void* const* d_in, const int* in_sizes, int n_in,
                              void* d_out, int out_size) {
    const float* x_in    = (const float*)d_in[0];   // (2048,64,64)
    const int*   sub_adj = (const int*)  d_in[1];   // (64,64)
    const int*   adj     = (const int*)  d_in[2];   // (2048,2048)
    const float* W_convs = (const float*)d_in[3];   // (3,4,64,64)
    const float* b_convs = (const float*)d_in[4];   // (3,4,64)
    const float* ln_g    = (const float*)d_in[5];   // (3,64,64)
    const float* ln_b    = (const float*)d_in[6];   // (3,64,64)
    const float* W_lin   = (const float*)d_in[7];   // (4096,64)
    const float* b_lin   = (const float*)d_in[8];   // (64)
    float* out = (float*)d_out;

    float *Af, *A2, *A3, *X, *B1, *B2, *Y, *Sn;
    cudaGetSymbolAddress((void**)&Af, g_Af);
    cudaGetSymbolAddress((void**)&A2, g_A2);
    cudaGetSymbolAddress((void**)&A3, g_A3);
    cudaGetSymbolAddress((void**)&X,  g_X);
    cudaGetSymbolAddress((void**)&B1, g_B1);
    cudaGetSymbolAddress((void**)&B2, g_B2);
    cudaGetSymbolAddress((void**)&Y,  g_Y);
    cudaGetSymbolAddress((void**)&Sn, g_Sn);

    // precompute: A as float, A^2, A^3 (exact integer GEMMs in tf32), Sn
    cast_i2f<<<(NN * NN) / 256, 256>>>(adj, Af);
    gemm_tf32<<<dim3(NN / 128, NN / 128), 256>>>(Af, Af, A2, NN, NN, NN);
    gemm_tf32<<<dim3(NN / 128, NN / 128), 256>>>(A2, Af, A3, NN, NN, NN);
    compute_sn<<<1, 64>>>(sub_adj, Sn);

    const dim3 gmeta(FDIM / 128, NN / 128);
    const int RB = (NN * MDIM) / 64;   // wgemm blocks = 2048
    for (int l = 0; l < 3; l++) {
        const float* curX = (l == 0) ? x_in : X;
        const float* Wl = W_convs + (long)l * 4 * 4096;

        // Y = curX @ W0
        wgemm64<<<RB, 256>>>(curX, Wl + 0 * 4096, Y, 0);
        // x1 = A @ x ; Y += x1 @ W1
        gemm_tf32<<<gmeta, 256>>>(Af, curX, B1, NN, FDIM, NN);
        wgemm64<<<RB, 256>>>(B1, Wl + 1 * 4096, Y, 1);
        // x2 = A^2 @ x1 ; Y += x2 @ W2
        gemm_tf32<<<gmeta, 256>>>(A2, B1, B2, NN, FDIM, NN);
        wgemm64<<<RB, 256>>>(B2, Wl + 2 * 4096, Y, 1);
        // x3 = A^3 @ x2 ; Y += x3 @ W3
        gemm_tf32<<<gmeta, 256>>>(A3, B2, B1, NN, FDIM, NN);
        wgemm64<<<RB, 256>>>(B1, Wl + 3 * 4096, Y, 1);

        // X = relu(LN(Sn @ Y + sum_i b_i))
        sn_ln_relu<<<NN, 256>>>(Y, Sn,
                                b_convs + (long)l * 256,
                                ln_g + (long)l * 4096,
                                ln_b + (long)l * 4096,
                                X);
    }

    final_gemm<<<NN / 16, 256>>>(X, W_lin, b_lin, out);
}

// round 7
// speedup vs baseline: 2.3020x; 1.2545x over previous
#include <cuda_runtime.h>
#include <cstdint>

// Problem constants
#define NN    2048          // meta nodes
#define MDIM  64            // subgraph nodes
#define DDIM  64            // channels
#define FDIM  4096          // MDIM*DDIM
#define OUTD  64
#define LN_EPS 1e-5f

// ------------------------- scratch (device globals; no allocation) ----------
__device__ float g_Af[NN * NN];     // A (row-major)
__device__ float g_AT[NN * NN];     // A^T
__device__ float g_A2[NN * NN];     // (A^2)^T
__device__ float g_A3[NN * NN];     // (A^3)^T
__device__ float g_X [NN * FDIM];
__device__ float g_B1[NN * FDIM];
__device__ float g_B2[NN * FDIM];
__device__ float g_Y [NN * FDIM];
__device__ float g_Sn[MDIM * MDIM];

// ------------------------- int32 -> float cast ------------------------------
__global__ void cast_i2f(const int* __restrict__ a, float* __restrict__ o) {
    int i = blockIdx.x * blockDim.x + threadIdx.x;
    o[i] = (float)a[i];
}

// transpose-cast: oT[j,i] = (float)a[i,j], 32x32 smem tiles
__global__ void cast_i2f_T(const int* __restrict__ a, float* __restrict__ oT) {
    __shared__ float tile[32][33];
    int bx = blockIdx.x * 32, by = blockIdx.y * 32;
    int tx = threadIdx.x, ty = threadIdx.y;            // 32x8
    #pragma unroll
    for (int j = 0; j < 32; j += 8)
        tile[ty + j][tx] = (float)a[(long)(by + ty + j) * NN + bx + tx];
    __syncthreads();
    #pragma unroll
    for (int j = 0; j < 32; j += 8)
        oT[(long)(bx + ty + j) * NN + by + tx] = tile[tx][ty + j];
}

// ------------------------- Sn = D^-1/2 (S+I) D^-1/2 -------------------------
__global__ void compute_sn(const int* __restrict__ sub_adj, float* __restrict__ Sn) {
    __shared__ float dinv[MDIM];
    int u = threadIdx.x;                 // 64 threads
    float s = 1.0f;                      // self loop
    for (int v = 0; v < MDIM; v++) s += (float)sub_adj[u * MDIM + v];
    dinv[u] = rsqrtf(s);
    __syncthreads();
    float du = dinv[u];
    for (int v = 0; v < MDIM; v++) {
        float a = (float)sub_adj[u * MDIM + v] + (u == v ? 1.0f : 0.0f);
        Sn[u * MDIM + v] = du * a * dinv[v];
    }
}

// ------------------------- mma / cp.async helpers ----------------------------
__device__ __forceinline__ void mma_tf32(float c[4], const uint32_t a[4],
                                         const uint32_t b[2]) {
    asm volatile(
        "mma.sync.aligned.m16n8k8.row.col.f32.tf32.tf32.f32 "
        "{%0,%1,%2,%3}, {%4,%5,%6,%7}, {%8,%9}, {%0,%1,%2,%3};\n"
        : "+f"(c[0]), "+f"(c[1]), "+f"(c[2]), "+f"(c[3])
        : "r"(a[0]), "r"(a[1]), "r"(a[2]), "r"(a[3]), "r"(b[0]), "r"(b[1]));
}

__device__ __forceinline__ void cp16(float* smem, const float* gmem) {
    uint32_t s = (uint32_t)__cvta_generic_to_shared(smem);
    asm volatile("cp.async.cg.shared.global [%0], [%1], 16;\n" :: "r"(s), "l"(gmem));
}
__device__ __forceinline__ void cp_commit() {
    asm volatile("cp.async.commit_group;\n");
}
template<int W> __device__ __forceinline__ void cp_wait() {
    asm volatile("cp.async.wait_group %0;\n" :: "n"(W));
}

// ---------------- tensor-core GEMM: C(MxN) = (AT)^T (MxK) * B(KxN) ----------
// fp32 in/out, tf32 mma (raw fp32 bits => truncation; exact for integer A).
// Block 128x128x32, 256 threads, warp tile 64x32, 3-stage cp.async pipeline.
// AT is the K x M row-major transpose of the left operand -> As[k][m] smem
// layout is a straight 16B copy. XOR-16 swizzle on m by bit4 of k.
#define TBK 32
#define STAGES 3
#define SPAD 136
#define GEMM_SMEM (STAGES * TBK * SPAD * 2 * 4)   // 104448 bytes

__global__ __launch_bounds__(256, 2)
void gemm_tt(const float* __restrict__ AT, const float* __restrict__ B,
             float* __restrict__ C, int M, int N, int K) {
    extern __shared__ float sm[];
    float (*As)[TBK][SPAD] = (float (*)[TBK][SPAD])sm;
    float (*Bs)[TBK][SPAD] = (float (*)[TBK][SPAD])(sm + STAGES * TBK * SPAD);

    const int t  = threadIdx.x;
    const int bm = blockIdx.y * 128;
    const int bn = blockIdx.x * 128;
    const int lane = t & 31;
    const int g  = lane >> 2;           // 0..7
    const int tg = lane & 3;            // 0..3
    const int w  = t >> 5;
    const int wm = (w >> 2) * 64;       // 0 or 64
    const int wn = (w & 3) * 32;        // 0,32,64,96

    // A^T staging: row kk = t>>3 (0..31), 4 chunks of 16B along m
    const int akk = t >> 3;
    const int ac0 = (t & 7) * 4;
    const int asw = ((akk >> 4) & 1) << 4;
    const float* Ag = AT + (long)akk * M + bm;
    // B staging: rows t>>5 + 8j, 16B chunk along n
    const int bkk = t >> 5;
    const int bn4 = (t & 31) * 4;
    const float* Bg = B + (long)bkk * N + bn + bn4;

    float c[4][4][4];
    #pragma unroll
    for (int im = 0; im < 4; im++)
        #pragma unroll
        for (int in = 0; in < 4; in++) {
            c[im][in][0] = 0.f; c[im][in][1] = 0.f;
            c[im][in][2] = 0.f; c[im][in][3] = 0.f;
        }

    const int ktiles = K / TBK;

    // prologue: issue first STAGES-1 tiles
    #pragma unroll
    for (int s = 0; s < STAGES - 1; s++) {
        const long k0 = (long)s * TBK;
        #pragma unroll
        for (int j = 0; j < 4; j++)
            cp16(&As[s][akk][(ac0 + 32 * j) ^ asw], Ag + k0 * M + ac0 + 32 * j);
        #pragma unroll
        for (int j = 0; j < 4; j++)
            cp16(&Bs[s][bkk + 8 * j][bn4], Bg + (k0 + 8 * j) * N);
        cp_commit();
    }

    for (int i = 0; i < ktiles; i++) {
        if (i + STAGES - 1 < ktiles) cp_wait<STAGES - 2>(); else cp_wait<0>();
        __syncthreads();

        // issue tile i+STAGES-1 into the slot freed at iteration i-1
        const int nx = i + STAGES - 1;
        if (nx < ktiles) {
            const int st = nx % STAGES;
            const long k0 = (long)nx * TBK;
            #pragma unroll
            for (int j = 0; j < 4; j++)
                cp16(&As[st][akk][(ac0 + 32 * j) ^ asw], Ag + k0 * M + ac0 + 32 * j);
            #pragma unroll
            for (int j = 0; j < 4; j++)
                cp16(&Bs[st][bkk + 8 * j][bn4], Bg + (k0 + 8 * j) * N);
            cp_commit();
        }

        const int cur = i % STAGES;
        #pragma unroll
        for (int ks = 0; ks < 4; ks++) {
            const int kr = ks * 8;
            const int sw = (ks >> 1) << 4;
            uint32_t af[4][4], bf[4][2];
            #pragma unroll
            for (int im = 0; im < 4; im++) {
                const int m0 = (wm + im * 16 + g) ^ sw;
                const int m8 = (wm + im * 16 + g + 8) ^ sw;
                af[im][0] = __float_as_uint(As[cur][kr + tg    ][m0]);
                af[im][1] = __float_as_uint(As[cur][kr + tg    ][m8]);
                af[im][2] = __float_as_uint(As[cur][kr + tg + 4][m0]);
                af[im][3] = __float_as_uint(As[cur][kr + tg + 4][m8]);
            }
            #pragma unroll
            for (int in = 0; in < 4; in++) {
                const int nb = wn + in * 8 + g;
                bf[in][0] = __float_as_uint(Bs[cur][kr + tg    ][nb]);
                bf[in][1] = __float_as_uint(Bs[cur][kr + tg + 4][nb]);
            }
            #pragma unroll
            for (int im = 0; im < 4; im++)
                #pragma unroll
                for (int in = 0; in < 4; in++)
                    mma_tf32(c[im][in], af[im], bf[in]);
        }
    }

    #pragma unroll
    for (int im = 0; im < 4; im++) {
        const long row = bm + wm + im * 16 + g;
        #pragma unroll
        for (int in = 0; in < 4; in++) {
            const int col = bn + wn + in * 8 + 2 * tg;
            float* Cp = C + row * N + col;
            *(float2*)Cp           = make_float2(c[im][in][0], c[im][in][1]);
            *(float2*)(Cp + 8 * N) = make_float2(c[im][in][2], c[im][in][3]);
        }
    }
}

// ------------------- weight apply: Y(R,64) (+)= X(R,64) @ W(64,64) ----------
__global__ __launch_bounds__(256)
void wgemm64(const float* __restrict__ X, const float* __restrict__ W,
             float* __restrict__ Y, int accumulate) {
    __shared__ float Xs[64][68];
    __shared__ float Ws[64][64];
    const int t = threadIdx.x;
    const long row0 = (long)blockIdx.x * 64;

    #pragma unroll
    for (int i = 0; i < 16; i++) {
        int idx = t + i * 256;
        ((float*)Ws)[idx] = W[idx];
        int r = idx >> 6, c = idx & 63;
        Xs[r][c] = X[(row0 + r) * 64 + c];
    }
    __syncthreads();

    const int r  = t >> 2;
    const int c0 = (t & 3) * 16;
    float acc[16];
    if (accumulate) {
        #pragma unroll
        for (int q = 0; q < 4; q++)
            *(float4*)&acc[q * 4] = *(const float4*)(Y + (row0 + r) * 64 + c0 + q * 4);
    } else {
        #pragma unroll
        for (int j = 0; j < 16; j++) acc[j] = 0.0f;
    }
    #pragma unroll 8
    for (int d = 0; d < 64; d++) {
        float xv = Xs[r][d];
        #pragma unroll
        for (int j = 0; j < 16; j++) acc[j] += xv * Ws[d][c0 + j];
    }
    #pragma unroll
    for (int q = 0; q < 4; q++)
        *(float4*)(Y + (row0 + r) * 64 + c0 + q * 4) = *(float4*)&acc[q * 4];
}

// -------- per-n: H = Sn @ Y[n] + bias_sum ; LayerNorm(m,d) ; ReLU -> X ------
__global__ __launch_bounds__(256)
void sn_ln_relu(const float* __restrict__ Y, const float* __restrict__ Sn,
                const float* __restrict__ bconv_l,   // (4,64)
                const float* __restrict__ gamma_l,   // (64,64)
                const float* __restrict__ beta_l,    // (64,64)
                float* __restrict__ Xout) {
    __shared__ float Ys[64][68];
    __shared__ float Sns[64][68];
    __shared__ float red[8];
    __shared__ float s_mu, s_rstd;

    const int n = blockIdx.x;
    const int t = threadIdx.x;
    const float* Yn = Y + (long)n * FDIM;

    #pragma unroll
    for (int i = 0; i < 16; i++) {
        int idx = t + i * 256;
        int r = idx >> 6, c = idx & 63;
        Ys[r][c]  = Yn[idx];
        Sns[r][c] = Sn[idx];
    }
    __syncthreads();

    const int u  = t >> 2;
    const int c0 = (t & 3) * 16;

    float h[16];
    #pragma unroll
    for (int j = 0; j < 16; j++)
        h[j] = bconv_l[c0 + j] + bconv_l[64 + c0 + j] +
               bconv_l[128 + c0 + j] + bconv_l[192 + c0 + j];

    #pragma unroll 8
    for (int v = 0; v < 64; v++) {
        float s = Sns[u][v];
        #pragma unroll
        for (int j = 0; j < 16; j++) h[j] += s * Ys[v][c0 + j];
    }

    const int lane = t & 31, wid = t >> 5;
    float lsum = 0.0f;
    #pragma unroll
    for (int j = 0; j < 16; j++) lsum += h[j];
    #pragma unroll
    for (int o = 16; o > 0; o >>= 1) lsum += __shfl_xor_sync(0xffffffffu, lsum, o);
    if (lane == 0) red[wid] = lsum;
    __syncthreads();
    if (t == 0) {
        float s = 0.0f;
        #pragma unroll
        for (int i = 0; i < 8; i++) s += red[i];
        s_mu = s * (1.0f / 4096.0f);
    }
    __syncthreads();
    const float mu = s_mu;

    float lv = 0.0f;
    #pragma unroll
    for (int j = 0; j < 16; j++) { float d = h[j] - mu; lv += d * d; }
    #pragma unroll
    for (int o = 16; o > 0; o >>= 1) lv += __shfl_xor_sync(0xffffffffu, lv, o);
    if (lane == 0) red[wid] = lv;
    __syncthreads();
    if (t == 0) {
        float s = 0.0f;
        #pragma unroll
        for (int i = 0; i < 8; i++) s += red[i];
        s_rstd = rsqrtf(s * (1.0f / 4096.0f) + LN_EPS);
    }
    __syncthreads();
    const float rstd = s_rstd;

    float* Xn = Xout + (long)n * FDIM + u * 64 + c0;
    const float* gp = gamma_l + u * 64 + c0;
    const float* bp = beta_l  + u * 64 + c0;
    #pragma unroll
    for (int j = 0; j < 16; j++) {
        float v = (h[j] - mu) * rstd * gp[j] + bp[j];
        Xn[j] = fmaxf(v, 0.0f);
    }
}

// ----------- readout: out(2048,64) = X(2048,4096) @ Wl(4096,64) + bl --------
__global__ __launch_bounds__(256)
void final_gemm(const float* __restrict__ X, const float* __restrict__ Wl,
                const float* __restrict__ bl, float* __restrict__ out) {
    __shared__ float Xs[16][128];
    __shared__ float Ws[128][68];
    const int t = threadIdx.x;
    const long m0 = (long)blockIdx.x * 16;
    const int r  = t >> 4;
    const int cq = (t & 15) * 4;

    float acc[4] = {0.f, 0.f, 0.f, 0.f};

    for (int k0 = 0; k0 < FDIM; k0 += 128) {
        #pragma unroll
        for (int i = 0; i < 2; i++) {
            int idx = t + i * 256;
            int rr = idx >> 5, cc = (idx & 31) * 4;
            *(float4*)&Xs[rr][cc] = *(const float4*)(X + (m0 + rr) * FDIM + k0 + cc);
        }
        #pragma unroll
        for (int i = 0; i < 8; i++) {
            int idx = t + i * 256;
            int kk = idx >> 4, cc = (idx & 15) * 4;
            float4 v = *(const float4*)(Wl + (long)(k0 + kk) * 64 + cc);
            Ws[kk][cc] = v.x; Ws[kk][cc + 1] = v.y; Ws[kk][cc + 2] = v.z; Ws[kk][cc + 3] = v.w;
        }
        __syncthreads();
        #pragma unroll 16
        for (int kk = 0; kk < 128; kk++) {
            float xv = Xs[r][kk];
            #pragma unroll
            for (int j = 0; j < 4; j++) acc[j] += xv * Ws[kk][cq + j];
        }
        __syncthreads();
    }
    float4 v = make_float4(acc[0] + bl[cq], acc[1] + bl[cq + 1],
                           acc[2] + bl[cq + 2], acc[3] + bl[cq + 3]);
    *(float4*)(out + (m0 + r) * 64 + cq) = v;
}

// ---------------------------------------------------------------------------
extern "C" void kernel_launch(void* const* d_in, const int* in_sizes, int n_in,
                              void* d_out, int out_size) {
    const float* x_in    = (const float*)d_in[0];   // (2048,64,64)
    const int*   sub_adj = (const int*)  d_in[1];   // (64,64)
    const int*   adj     = (const int*)  d_in[2];   // (2048,2048)
    const float* W_convs = (const float*)d_in[3];   // (3,4,64,64)
    const float* b_convs = (const float*)d_in[4];   // (3,4,64)
    const float* ln_g    = (const float*)d_in[5];   // (3,64,64)
    const float* ln_b    = (const float*)d_in[6];   // (3,64,64)
    const float* W_lin   = (const float*)d_in[7];   // (4096,64)
    const float* b_lin   = (const float*)d_in[8];   // (64)
    float* out = (float*)d_out;

    float *Af, *AT, *A2, *A3, *X, *B1, *B2, *Y, *Sn;
    cudaGetSymbolAddress((void**)&Af, g_Af);
    cudaGetSymbolAddress((void**)&AT, g_AT);
    cudaGetSymbolAddress((void**)&A2, g_A2);
    cudaGetSymbolAddress((void**)&A3, g_A3);
    cudaGetSymbolAddress((void**)&X,  g_X);
    cudaGetSymbolAddress((void**)&B1, g_B1);
    cudaGetSymbolAddress((void**)&B2, g_B2);
    cudaGetSymbolAddress((void**)&Y,  g_Y);
    cudaGetSymbolAddress((void**)&Sn, g_Sn);

    cudaFuncSetAttribute(gemm_tt, cudaFuncAttributeMaxDynamicSharedMemorySize,
                         GEMM_SMEM);

    // precompute: Af, AfT, (A^2)^T, (A^3)^T (all exact integer GEMMs), Sn
    cast_i2f<<<(NN * NN) / 256, 256>>>(adj, Af);
    cast_i2f_T<<<dim3(NN / 32, NN / 32), dim3(32, 8)>>>(adj, AT);
    // A2T = AfT @ AfT = (Af)^T @ AfT
    gemm_tt<<<dim3(NN / 128, NN / 128), 256, GEMM_SMEM>>>(Af, AT, A2, NN, NN, NN);
    // A3T = AfT @ A2T = (Af)^T @ A2T
    gemm_tt<<<dim3(NN / 128, NN / 128), 256, GEMM_SMEM>>>(Af, A2, A3, NN, NN, NN);
    compute_sn<<<1, 64>>>(sub_adj, Sn);

    const dim3 gmeta(FDIM / 128, NN / 128);
    const int RB = (NN * MDIM) / 64;   // wgemm blocks = 2048
    for (int l = 0; l < 3; l++) {
        const float* curX = (l == 0) ? x_in : X;
        const float* Wl = W_convs + (long)l * 4 * 4096;

        // Y = curX @ W0
        wgemm64<<<RB, 256>>>(curX, Wl + 0 * 4096, Y, 0);
        // x1 = A @ x ; Y += x1 @ W1
        gemm_tt<<<gmeta, 256, GEMM_SMEM>>>(AT, curX, B1, NN, FDIM, NN);
        wgemm64<<<RB, 256>>>(B1, Wl + 1 * 4096, Y, 1);
        // x2 = A^2 @ x1 ; Y += x2 @ W2
        gemm_tt<<<gmeta, 256, GEMM_SMEM>>>(A2, B1, B2, NN, FDIM, NN);
        wgemm64<<<RB, 256>>>(B2, Wl + 2 * 4096, Y, 1);
        // x3 = A^3 @ x2 ; Y += x3 @ W3
        gemm_tt<<<gmeta, 256, GEMM_SMEM>>>(A3, B2, B1, NN, FDIM, NN);
        wgemm64<<<RB, 256>>>(B1, Wl + 3 * 4096, Y, 1);

        // X = relu(LN(Sn @ Y + sum_i b_i))
        sn_ln_relu<<<NN, 256>>>(Y, Sn,
                                b_convs + (long)l * 256,
                                ln_g + (long)l * 4096,
                                ln_b + (long)l * 4096,
                                X);
    }

    final_gemm<<<NN / 16, 256>>>(X, W_lin, b_lin, out);
}

// round 8
// speedup vs baseline: 3.0343x; 1.3181x over previous
#include <cuda_runtime.h>
#include <cstdint>

// Problem constants
#define NN    2048          // meta nodes
#define MDIM  64            // subgraph nodes
#define DDIM  64            // channels
#define FDIM  4096          // MDIM*DDIM
#define OUTD  64
#define LN_EPS 1e-5f

// ------------------------- scratch (device globals; no allocation) ----------
__device__ float g_Af[NN * NN];     // A (row-major)
__device__ float g_AT[NN * NN];     // A^T
__device__ float g_A2[NN * NN];     // (A^2)^T
__device__ float g_A3[NN * NN];     // (A^3)^T
__device__ float g_X [NN * FDIM];
__device__ float g_B1[NN * FDIM];
__device__ float g_B2[NN * FDIM];
__device__ float g_B3[NN * FDIM];
__device__ float g_Sn[MDIM * MDIM];

// ------------------------- int32 -> float cast ------------------------------
__global__ void cast_i2f(const int* __restrict__ a, float* __restrict__ o) {
    int i = blockIdx.x * blockDim.x + threadIdx.x;
    o[i] = (float)a[i];
}

// transpose-cast: oT[j,i] = (float)a[i,j], 32x32 smem tiles
__global__ void cast_i2f_T(const int* __restrict__ a, float* __restrict__ oT) {
    __shared__ float tile[32][33];
    int bx = blockIdx.x * 32, by = blockIdx.y * 32;
    int tx = threadIdx.x, ty = threadIdx.y;            // 32x8
    #pragma unroll
    for (int j = 0; j < 32; j += 8)
        tile[ty + j][tx] = (float)a[(long)(by + ty + j) * NN + bx + tx];
    __syncthreads();
    #pragma unroll
    for (int j = 0; j < 32; j += 8)
        oT[(long)(bx + ty + j) * NN + by + tx] = tile[tx][ty + j];
}

// ------------------------- Sn = D^-1/2 (S+I) D^-1/2 -------------------------
__global__ void compute_sn(const int* __restrict__ sub_adj, float* __restrict__ Sn) {
    __shared__ float dinv[MDIM];
    int u = threadIdx.x;                 // 64 threads
    float s = 1.0f;                      // self loop
    for (int v = 0; v < MDIM; v++) s += (float)sub_adj[u * MDIM + v];
    dinv[u] = rsqrtf(s);
    __syncthreads();
    float du = dinv[u];
    for (int v = 0; v < MDIM; v++) {
        float a = (float)sub_adj[u * MDIM + v] + (u == v ? 1.0f : 0.0f);
        Sn[u * MDIM + v] = du * a * dinv[v];
    }
}

// ------------------------- mma / cp.async / f32x2 helpers --------------------
__device__ __forceinline__ void mma_tf32(float c[4], const uint32_t a[4],
                                         const uint32_t b[2]) {
    asm volatile(
        "mma.sync.aligned.m16n8k8.row.col.f32.tf32.tf32.f32 "
        "{%0,%1,%2,%3}, {%4,%5,%6,%7}, {%8,%9}, {%0,%1,%2,%3};\n"
        : "+f"(c[0]), "+f"(c[1]), "+f"(c[2]), "+f"(c[3])
        : "r"(a[0]), "r"(a[1]), "r"(a[2]), "r"(a[3]), "r"(b[0]), "r"(b[1]));
}

__device__ __forceinline__ void cp16(float* smem, const float* gmem) {
    uint32_t s = (uint32_t)__cvta_generic_to_shared(smem);
    asm volatile("cp.async.cg.shared.global [%0], [%1], 16;\n" :: "r"(s), "l"(gmem));
}
__device__ __forceinline__ void cp_commit() {
    asm volatile("cp.async.commit_group;\n");
}
template<int W> __device__ __forceinline__ void cp_wait() {
    asm volatile("cp.async.wait_group %0;\n" :: "n"(W));
}

__device__ __forceinline__ unsigned long long pack2(float x) {
    unsigned long long r;
    asm("mov.b64 %0, {%1, %1};" : "=l"(r) : "f"(x));
    return r;
}
__device__ __forceinline__ unsigned long long pack2f(float lo, float hi) {
    unsigned long long r;
    asm("mov.b64 %0, {%1, %2};" : "=l"(r) : "f"(lo), "f"(hi));
    return r;
}
__device__ __forceinline__ void fma2(unsigned long long& d, unsigned long long a,
                                     unsigned long long b) {
    asm("fma.rn.f32x2 %0, %1, %2, %0;" : "+l"(d) : "l"(a), "l"(b));
}
__device__ __forceinline__ float2 unpack2(unsigned long long v) {
    float2 f;
    asm("mov.b64 {%0, %1}, %2;" : "=f"(f.x), "=f"(f.y) : "l"(v));
    return f;
}

// ---------------- tensor-core GEMM: C(MxN) = (AT)^T (MxK) * B(KxN) ----------
// fp32 in/out, tf32 mma (raw fp32 bits => truncation; exact for integer A).
// Block 128x128x32, 256 threads, warp tile 64x32, 3-stage cp.async pipeline.
#define TBK 32
#define STAGES 3
#define SPAD 136
#define GEMM_SMEM (STAGES * TBK * SPAD * 2 * 4)   // 104448 bytes

__global__ __launch_bounds__(256, 2)
void gemm_tt(const float* __restrict__ AT, const float* __restrict__ B,
             float* __restrict__ C, int M, int N, int K) {
    extern __shared__ float sm[];
    float (*As)[TBK][SPAD] = (float (*)[TBK][SPAD])sm;
    float (*Bs)[TBK][SPAD] = (float (*)[TBK][SPAD])(sm + STAGES * TBK * SPAD);

    const int t  = threadIdx.x;
    const int bm = blockIdx.y * 128;
    const int bn = blockIdx.x * 128;
    const int lane = t & 31;
    const int g  = lane >> 2;           // 0..7
    const int tg = lane & 3;            // 0..3
    const int w  = t >> 5;
    const int wm = (w >> 2) * 64;       // 0 or 64
    const int wn = (w & 3) * 32;        // 0,32,64,96

    const int akk = t >> 3;
    const int ac0 = (t & 7) * 4;
    const int asw = ((akk >> 4) & 1) << 4;
    const float* Ag = AT + (long)akk * M + bm;
    const int bkk = t >> 5;
    const int bn4 = (t & 31) * 4;
    const float* Bg = B + (long)bkk * N + bn + bn4;

    float c[4][4][4];
    #pragma unroll
    for (int im = 0; im < 4; im++)
        #pragma unroll
        for (int in = 0; in < 4; in++) {
            c[im][in][0] = 0.f; c[im][in][1] = 0.f;
            c[im][in][2] = 0.f; c[im][in][3] = 0.f;
        }

    const int ktiles = K / TBK;

    #pragma unroll
    for (int s = 0; s < STAGES - 1; s++) {
        const long k0 = (long)s * TBK;
        #pragma unroll
        for (int j = 0; j < 4; j++)
            cp16(&As[s][akk][(ac0 + 32 * j) ^ asw], Ag + k0 * M + ac0 + 32 * j);
        #pragma unroll
        for (int j = 0; j < 4; j++)
            cp16(&Bs[s][bkk + 8 * j][bn4], Bg + (k0 + 8 * j) * N);
        cp_commit();
    }

    for (int i = 0; i < ktiles; i++) {
        if (i + STAGES - 1 < ktiles) cp_wait<STAGES - 2>(); else cp_wait<0>();
        __syncthreads();

        const int nx = i + STAGES - 1;
        if (nx < ktiles) {
            const int st = nx % STAGES;
            const long k0 = (long)nx * TBK;
            #pragma unroll
            for (int j = 0; j < 4; j++)
                cp16(&As[st][akk][(ac0 + 32 * j) ^ asw], Ag + k0 * M + ac0 + 32 * j);
            #pragma unroll
            for (int j = 0; j < 4; j++)
                cp16(&Bs[st][bkk + 8 * j][bn4], Bg + (k0 + 8 * j) * N);
            cp_commit();
        }

        const int cur = i % STAGES;
        #pragma unroll
        for (int ks = 0; ks < 4; ks++) {
            const int kr = ks * 8;
            const int sw = (ks >> 1) << 4;
            uint32_t af[4][4], bf[4][2];
            #pragma unroll
            for (int im = 0; im < 4; im++) {
                const int m0 = (wm + im * 16 + g) ^ sw;
                const int m8 = (wm + im * 16 + g + 8) ^ sw;
                af[im][0] = __float_as_uint(As[cur][kr + tg    ][m0]);
                af[im][1] = __float_as_uint(As[cur][kr + tg    ][m8]);
                af[im][2] = __float_as_uint(As[cur][kr + tg + 4][m0]);
                af[im][3] = __float_as_uint(As[cur][kr + tg + 4][m8]);
            }
            #pragma unroll
            for (int in = 0; in < 4; in++) {
                const int nb = wn + in * 8 + g;
                bf[in][0] = __float_as_uint(Bs[cur][kr + tg    ][nb]);
                bf[in][1] = __float_as_uint(Bs[cur][kr + tg + 4][nb]);
            }
            #pragma unroll
            for (int im = 0; im < 4; im++)
                #pragma unroll
                for (int in = 0; in < 4; in++)
                    mma_tf32(c[im][in], af[im], bf[in]);
        }
    }

    #pragma unroll
    for (int im = 0; im < 4; im++) {
        const long row = bm + wm + im * 16 + g;
        #pragma unroll
        for (int in = 0; in < 4; in++) {
            const int col = bn + wn + in * 8 + 2 * tg;
            float* Cp = C + row * N + col;
            *(float2*)Cp           = make_float2(c[im][in][0], c[im][in][1]);
            *(float2*)(Cp + 8 * N) = make_float2(c[im][in][2], c[im][in][3]);
        }
    }
}

// ---- fused per-layer epilogue: T = sum_i xi@Wi ; h = Sn@T + b ; LN ; ReLU ---
// One block per n. 256 threads: u = t>>2 (row), q = t&3.
// Column mapping per thread: c = q*4 + 16*v + j  (v=0..3, j=0..3).
// Inner loops: LDS.128 weight loads (bank-conflict-free) + packed fma.rn.f32x2.
#define EPI_TILE (64 * 68)
#define EPI_SMEM (4 * EPI_TILE * 4)          // Xs, Ws, Ts, Sns = 69632 bytes

__global__ __launch_bounds__(256)
void layer_epilogue(const float* __restrict__ x0, const float* __restrict__ x1,
                    const float* __restrict__ x2, const float* __restrict__ x3,
                    const float* __restrict__ Wl,       // (4,64,64)
                    const float* __restrict__ Sn,       // (64,64)
                    const float* __restrict__ bconv_l,  // (4,64)
                    const float* __restrict__ gamma_l,  // (64,64)
                    const float* __restrict__ beta_l,   // (64,64)
                    float* __restrict__ Xout) {
    extern __shared__ float esm[];
    float (*Xs)[68]  = (float (*)[68])(esm);
    float (*Ws)[68]  = (float (*)[68])(esm + EPI_TILE);
    float (*Ts)[68]  = (float (*)[68])(esm + 2 * EPI_TILE);
    float (*Sns)[68] = (float (*)[68])(esm + 3 * EPI_TILE);
    __shared__ float red[8];
    __shared__ float s_mu, s_rstd;

    const int n = blockIdx.x;
    const int t = threadIdx.x;
    const int u = t >> 2;
    const int q = t & 3;
    const long base = (long)n * FDIM;

    #pragma unroll
    for (int i = 0; i < 16; i++) {
        int idx = t + i * 256;
        Sns[idx >> 6][idx & 63] = Sn[idx];
    }

    unsigned long long acc[4][2];
    #pragma unroll
    for (int v = 0; v < 4; v++) { acc[v][0] = 0ull; acc[v][1] = 0ull; }

    const float* xp[4] = { x0 + base, x1 + base, x2 + base, x3 + base };

    for (int i = 0; i < 4; i++) {
        __syncthreads();                       // protect Xs/Ws reuse
        const float* xg = xp[i];
        const float* wg = Wl + i * 4096;
        #pragma unroll
        for (int r = 0; r < 16; r++) {
            int idx = t + r * 256;
            Xs[idx >> 6][idx & 63] = xg[idx];
            Ws[idx >> 6][idx & 63] = wg[idx];
        }
        __syncthreads();
        #pragma unroll 8
        for (int k = 0; k < 64; k++) {
            unsigned long long xv = pack2(Xs[u][k]);
            #pragma unroll
            for (int v = 0; v < 4; v++) {
                ulonglong2 w = *(const ulonglong2*)&Ws[k][q * 4 + 16 * v];
                fma2(acc[v][0], xv, w.x);
                fma2(acc[v][1], xv, w.y);
            }
        }
    }

    // write T tile to smem
    #pragma unroll
    for (int v = 0; v < 4; v++) {
        float2 a0 = unpack2(acc[v][0]);
        float2 a1 = unpack2(acc[v][1]);
        *(float4*)&Ts[u][q * 4 + 16 * v] = make_float4(a0.x, a0.y, a1.x, a1.y);
    }
    __syncthreads();

    // h = bias_sum + Sn @ T
    unsigned long long h2[4][2];
    #pragma unroll
    for (int v = 0; v < 4; v++)
        #pragma unroll
        for (int jj = 0; jj < 2; jj++) {
            int c = q * 4 + 16 * v + 2 * jj;
            float b0 = bconv_l[c]     + bconv_l[64 + c]
                     + bconv_l[128 + c] + bconv_l[192 + c];
            float b1 = bconv_l[c + 1] + bconv_l[64 + c + 1]
                     + bconv_l[128 + c + 1] + bconv_l[192 + c + 1];
            h2[v][jj] = pack2f(b0, b1);
        }
    #pragma unroll 8
    for (int k = 0; k < 64; k++) {
        unsigned long long sv = pack2(Sns[u][k]);
        #pragma unroll
        for (int v = 0; v < 4; v++) {
            ulonglong2 w = *(const ulonglong2*)&Ts[k][q * 4 + 16 * v];
            fma2(h2[v][0], sv, w.x);
            fma2(h2[v][1], sv, w.y);
        }
    }

    float h[16];
    #pragma unroll
    for (int v = 0; v < 4; v++) {
        float2 a0 = unpack2(h2[v][0]);
        float2 a1 = unpack2(h2[v][1]);
        h[4 * v + 0] = a0.x; h[4 * v + 1] = a0.y;
        h[4 * v + 2] = a1.x; h[4 * v + 3] = a1.y;
    }

    // block mean
    const int lane = t & 31, wid = t >> 5;
    float lsum = 0.0f;
    #pragma unroll
    for (int j = 0; j < 16; j++) lsum += h[j];
    #pragma unroll
    for (int o = 16; o > 0; o >>= 1) lsum += __shfl_xor_sync(0xffffffffu, lsum, o);
    if (lane == 0) red[wid] = lsum;
    __syncthreads();
    if (t == 0) {
        float s = 0.0f;
        #pragma unroll
        for (int i = 0; i < 8; i++) s += red[i];
        s_mu = s * (1.0f / 4096.0f);
    }
    __syncthreads();
    const float mu = s_mu;

    // block variance (two-pass)
    float lv = 0.0f;
    #pragma unroll
    for (int j = 0; j < 16; j++) { float d = h[j] - mu; lv += d * d; }
    #pragma unroll
    for (int o = 16; o > 0; o >>= 1) lv += __shfl_xor_sync(0xffffffffu, lv, o);
    if (lane == 0) red[wid] = lv;
    __syncthreads();
    if (t == 0) {
        float s = 0.0f;
        #pragma unroll
        for (int i = 0; i < 8; i++) s += red[i];
        s_rstd = rsqrtf(s * (1.0f / 4096.0f) + LN_EPS);
    }
    __syncthreads();
    const float rstd = s_rstd;

    #pragma unroll
    for (int v = 0; v < 4; v++) {
        const int c = q * 4 + 16 * v;
        const float4 g4 = *(const float4*)(gamma_l + u * 64 + c);
        const float4 b4 = *(const float4*)(beta_l  + u * 64 + c);
        float4 o;
        o.x = fmaxf((h[4 * v + 0] - mu) * rstd * g4.x + b4.x, 0.0f);
        o.y = fmaxf((h[4 * v + 1] - mu) * rstd * g4.y + b4.y, 0.0f);
        o.z = fmaxf((h[4 * v + 2] - mu) * rstd * g4.z + b4.z, 0.0f);
        o.w = fmaxf((h[4 * v + 3] - mu) * rstd * g4.w + b4.w, 0.0f);
        *(float4*)(Xout + base + u * 64 + c) = o;
    }
}

// ----------- readout: out(2048,64) = X(2048,4096) @ Wl(4096,64) + bl --------
__global__ __launch_bounds__(256)
void final_gemm(const float* __restrict__ X, const float* __restrict__ Wl,
                const float* __restrict__ bl, float* __restrict__ out) {
    __shared__ float Xs[16][128];
    __shared__ float Ws[128][68];
    const int t = threadIdx.x;
    const long m0 = (long)blockIdx.x * 16;
    const int r  = t >> 4;
    const int cq = (t & 15) * 4;

    float acc[4] = {0.f, 0.f, 0.f, 0.f};

    for (int k0 = 0; k0 < FDIM; k0 += 128) {
        #pragma unroll
        for (int i = 0; i < 2; i++) {
            int idx = t + i * 256;
            int rr = idx >> 5, cc = (idx & 31) * 4;
            *(float4*)&Xs[rr][cc] = *(const float4*)(X + (m0 + rr) * FDIM + k0 + cc);
        }
        #pragma unroll
        for (int i = 0; i < 8; i++) {
            int idx = t + i * 256;
            int kk = idx >> 4, cc = (idx & 15) * 4;
            float4 v = *(const float4*)(Wl + (long)(k0 + kk) * 64 + cc);
            Ws[kk][cc] = v.x; Ws[kk][cc + 1] = v.y; Ws[kk][cc + 2] = v.z; Ws[kk][cc + 3] = v.w;
        }
        __syncthreads();
        #pragma unroll 16
        for (int kk = 0; kk < 128; kk++) {
            float xv = Xs[r][kk];
            #pragma unroll
            for (int j = 0; j < 4; j++) acc[j] += xv * Ws[kk][cq + j];
        }
        __syncthreads();
    }
    float4 v = make_float4(acc[0] + bl[cq], acc[1] + bl[cq + 1],
                           acc[2] + bl[cq + 2], acc[3] + bl[cq + 3]);
    *(float4*)(out + (m0 + r) * 64 + cq) = v;
}

// ---------------------------------------------------------------------------
extern "C" void kernel_launch(void* const* d_in, const int* in_sizes, int n_in,
                              void* d_out, int out_size) {
    const float* x_in    = (const float*)d_in[0];   // (2048,64,64)
    const int*   sub_adj = (const int*)  d_in[1];   // (64,64)
    const int*   adj     = (const int*)  d_in[2];   // (2048,2048)
    const float* W_convs = (const float*)d_in[3];   // (3,4,64,64)
    const float* b_convs = (const float*)d_in[4];   // (3,4,64)
    const float* ln_g    = (const float*)d_in[5];   // (3,64,64)
    const float* ln_b    = (const float*)d_in[6];   // (3,64,64)
    const float* W_lin   = (const float*)d_in[7];   // (4096,64)
    const float* b_lin   = (const float*)d_in[8];   // (64)
    float* out = (float*)d_out;

    float *Af, *AT, *A2, *A3, *X, *B1, *B2, *B3, *Sn;
    cudaGetSymbolAddress((void**)&Af, g_Af);
    cudaGetSymbolAddress((void**)&AT, g_AT);
    cudaGetSymbolAddress((void**)&A2, g_A2);
    cudaGetSymbolAddress((void**)&A3, g_A3);
    cudaGetSymbolAddress((void**)&X,  g_X);
    cudaGetSymbolAddress((void**)&B1, g_B1);
    cudaGetSymbolAddress((void**)&B2, g_B2);
    cudaGetSymbolAddress((void**)&B3, g_B3);
    cudaGetSymbolAddress((void**)&Sn, g_Sn);

    cudaFuncSetAttribute(gemm_tt, cudaFuncAttributeMaxDynamicSharedMemorySize,
                         GEMM_SMEM);
    cudaFuncSetAttribute(layer_epilogue,
                         cudaFuncAttributeMaxDynamicSharedMemorySize, EPI_SMEM);

    // precompute: Af, AfT, (A^2)^T, (A^3)^T (all exact integer GEMMs), Sn
    cast_i2f<<<(NN * NN) / 256, 256>>>(adj, Af);
    cast_i2f_T<<<dim3(NN / 32, NN / 32), dim3(32, 8)>>>(adj, AT);
    gemm_tt<<<dim3(NN / 128, NN / 128), 256, GEMM_SMEM>>>(Af, AT, A2, NN, NN, NN);
    gemm_tt<<<dim3(NN / 128, NN / 128), 256, GEMM_SMEM>>>(Af, A2, A3, NN, NN, NN);
    compute_sn<<<1, 64>>>(sub_adj, Sn);

    const dim3 gmeta(FDIM / 128, NN / 128);
    for (int l = 0; l < 3; l++) {
        const float* curX = (l == 0) ? x_in : X;
        const float* Wl = W_convs + (long)l * 4 * 4096;

        // x1 = A @ x ; x2 = A^2 @ x1 ; x3 = A^3 @ x2
        gemm_tt<<<gmeta, 256, GEMM_SMEM>>>(AT, curX, B1, NN, FDIM, NN);
        gemm_tt<<<gmeta, 256, GEMM_SMEM>>>(A2, B1,  B2, NN, FDIM, NN);
        gemm_tt<<<gmeta, 256, GEMM_SMEM>>>(A3, B2,  B3, NN, FDIM, NN);

        // X = relu(LN(Sn @ (sum_i xi Wi) + sum_i b_i))
        layer_epilogue<<<NN, 256, EPI_SMEM>>>(curX, B1, B2, B3, Wl, Sn,
                                              b_convs + (long)l * 256,
                                              ln_g + (long)l * 4096,
                                              ln_b + (long)l * 4096,
                                              X);
    }

    final_gemm<<<NN / 16, 256>>>(X, W_lin, b_lin, out);
}

// round 10
// speedup vs baseline: 3.1718x; 1.0453x over previous
#include <cuda_runtime.h>
#include <cstdint>

// Problem constants
#define NN    2048          // meta nodes
#define MDIM  64            // subgraph nodes
#define DDIM  64            // channels
#define FDIM  4096          // MDIM*DDIM
#define OUTD  64
#define LN_EPS 1e-5f

// ------------------------- scratch (device globals; no allocation) ----------
__device__ float g_Af[NN * NN];     // A (row-major)
__device__ float g_AT[NN * NN];     // A^T
__device__ float g_A2[NN * NN];     // (A^2)^T
__device__ float g_A3[NN * NN];     // (A^3)^T
__device__ float g_X [NN * FDIM];
__device__ float g_B1[NN * FDIM];
__device__ float g_B2[NN * FDIM];
__device__ float g_B3[NN * FDIM];
__device__ float g_Sn[MDIM * MDIM];

// ------------------------- int32 -> float cast ------------------------------
__global__ void cast_i2f(const int* __restrict__ a, float* __restrict__ o) {
    int i = blockIdx.x * blockDim.x + threadIdx.x;
    o[i] = (float)a[i];
}

// transpose-cast: oT[j,i] = (float)a[i,j], 32x32 smem tiles
__global__ void cast_i2f_T(const int* __restrict__ a, float* __restrict__ oT) {
    __shared__ float tile[32][33];
    int bx = blockIdx.x * 32, by = blockIdx.y * 32;
    int tx = threadIdx.x, ty = threadIdx.y;            // 32x8
    #pragma unroll
    for (int j = 0; j < 32; j += 8)
        tile[ty + j][tx] = (float)a[(long)(by + ty + j) * NN + bx + tx];
    __syncthreads();
    #pragma unroll
    for (int j = 0; j < 32; j += 8)
        oT[(long)(bx + ty + j) * NN + by + tx] = tile[tx][ty + j];
}

// ------------------------- Sn = D^-1/2 (S+I) D^-1/2 -------------------------
__global__ void compute_sn(const int* __restrict__ sub_adj, float* __restrict__ Sn) {
    __shared__ float dinv[MDIM];
    int u = threadIdx.x;
    float s = 1.0f;
    for (int v = 0; v < MDIM; v++) s += (float)sub_adj[u * MDIM + v];
    dinv[u] = rsqrtf(s);
    __syncthreads();
    float du = dinv[u];
    for (int v = 0; v < MDIM; v++) {
        float a = (float)sub_adj[u * MDIM + v] + (u == v ? 1.0f : 0.0f);
        Sn[u * MDIM + v] = du * a * dinv[v];
    }
}

// ------------------------- mma / cp.async / f32x2 helpers --------------------
__device__ __forceinline__ void mma_tf32(float c[4], const uint32_t a[4],
                                         const uint32_t b[2]) {
    asm volatile(
        "mma.sync.aligned.m16n8k8.row.col.f32.tf32.tf32.f32 "
        "{%0,%1,%2,%3}, {%4,%5,%6,%7}, {%8,%9}, {%0,%1,%2,%3};\n"
        : "+f"(c[0]), "+f"(c[1]), "+f"(c[2]), "+f"(c[3])
        : "r"(a[0]), "r"(a[1]), "r"(a[2]), "r"(a[3]), "r"(b[0]), "r"(b[1]));
}

__device__ __forceinline__ void cp16(float* smem, const float* gmem) {
    uint32_t s = (uint32_t)__cvta_generic_to_shared(smem);
    asm volatile("cp.async.cg.shared.global [%0], [%1], 16;\n" :: "r"(s), "l"(gmem));
}
__device__ __forceinline__ void cp_commit() {
    asm volatile("cp.async.commit_group;\n");
}
template<int W> __device__ __forceinline__ void cp_wait() {
    asm volatile("cp.async.wait_group %0;\n" :: "n"(W));
}

__device__ __forceinline__ unsigned long long pack2(float x) {
    unsigned long long r;
    asm("mov.b64 %0, {%1, %1};" : "=l"(r) : "f"(x));
    return r;
}
__device__ __forceinline__ unsigned long long pack2f(float lo, float hi) {
    unsigned long long r;
    asm("mov.b64 %0, {%1, %2};" : "=l"(r) : "f"(lo), "f"(hi));
    return r;
}
__device__ __forceinline__ void fma2(unsigned long long& d, unsigned long long a,
                                     unsigned long long b) {
    asm("fma.rn.f32x2 %0, %1, %2, %0;" : "+l"(d) : "l"(a), "l"(b));
}
__device__ __forceinline__ float2 unpack2(unsigned long long v) {
    float2 f;
    asm("mov.b64 {%0, %1}, %2;" : "=f"(f.x), "=f"(f.y) : "l"(v));
    return f;
}

// ---------------- tensor-core GEMM: C(MxN) = (AT)^T (MxK) * B(KxN) ----------
// fp32 in/out, tf32 mma (raw fp32 bits => truncation; exact for integer A).
// Block tile 128x128x32, 128 threads (4 warps, 2x2 grid), warp tile 64x64.
// 3-stage cp.async pipeline. AT is the K x M transpose of the left operand.
#define TBK 32
#define STAGES 3
#define SPAD 136
#define GEMM_SMEM (STAGES * TBK * SPAD * 2 * 4)   // 104448 bytes

__global__ __launch_bounds__(128, 2)
void gemm_tt(const float* __restrict__ AT, const float* __restrict__ B,
             float* __restrict__ C, int M, int N, int K) {
    extern __shared__ float sm[];
    float (*As)[TBK][SPAD] = (float (*)[TBK][SPAD])sm;
    float (*Bs)[TBK][SPAD] = (float (*)[TBK][SPAD])(sm + STAGES * TBK * SPAD);

    const int t  = threadIdx.x;               // 0..127
    const int bm = blockIdx.y * 128;
    const int bn = blockIdx.x * 128;
    const int lane = t & 31;
    const int g  = lane >> 2;                 // 0..7
    const int tg = lane & 3;                  // 0..3
    const int w  = t >> 5;                    // 0..3
    const int wm = (w >> 1) * 64;             // 0 or 64
    const int wn = (w & 1) * 64;              // 0 or 64

    // A^T staging: thread covers k-rows {akk, akk+16}, 4 x 16B chunks along m
    const int akk = t >> 3;                   // 0..15
    const int ac0 = (t & 7) * 4;              // 0..28
    const float* Ag = AT + (long)akk * M + bm;
    // B staging: thread covers k-rows bkk+4j (j=0..7), one 16B chunk along n
    const int bkk = t >> 5;                   // 0..3
    const int bn4 = (t & 31) * 4;
    const float* Bg = B + (long)bkk * N + bn + bn4;

    float c[4][8][4];
    #pragma unroll
    for (int im = 0; im < 4; im++)
        #pragma unroll
        for (int in = 0; in < 8; in++) {
            c[im][in][0] = 0.f; c[im][in][1] = 0.f;
            c[im][in][2] = 0.f; c[im][in][3] = 0.f;
        }

    const int ktiles = K / TBK;

    // prologue: issue first STAGES-1 tiles
    #pragma unroll
    for (int s = 0; s < STAGES - 1; s++) {
        const long k0 = (long)s * TBK;
        #pragma unroll
        for (int j = 0; j < 4; j++) {
            cp16(&As[s][akk][(ac0 + 32 * j)],
                 Ag + k0 * M + ac0 + 32 * j);
            cp16(&As[s][akk + 16][(ac0 + 32 * j) ^ 16],
                 Ag + (k0 + 16) * M + ac0 + 32 * j);
        }
        #pragma unroll
        for (int j = 0; j < 8; j++)
            cp16(&Bs[s][bkk + 4 * j][bn4], Bg + (k0 + 4 * j) * N);
        cp_commit();
    }

    for (int i = 0; i < ktiles; i++) {
        if (i + STAGES - 1 < ktiles) cp_wait<STAGES - 2>(); else cp_wait<0>();
        __syncthreads();

        // issue tile i+STAGES-1 into the slot freed at iteration i-1
        const int nx = i + STAGES - 1;
        if (nx < ktiles) {
            const int st = nx % STAGES;
            const long k0 = (long)nx * TBK;
            #pragma unroll
            for (int j = 0; j < 4; j++) {
                cp16(&As[st][akk][(ac0 + 32 * j)],
                     Ag + k0 * M + ac0 + 32 * j);
                cp16(&As[st][akk + 16][(ac0 + 32 * j) ^ 16],
                     Ag + (k0 + 16) * M + ac0 + 32 * j);
            }
            #pragma unroll
            for (int j = 0; j < 8; j++)
                cp16(&Bs[st][bkk + 4 * j][bn4], Bg + (k0 + 4 * j) * N);
            cp_commit();
        }

        const int cur = i % STAGES;
        #pragma unroll
        for (int ks = 0; ks < 4; ks++) {
            const int kr = ks * 8;
            const int sw = (ks >> 1) << 4;
            uint32_t af[4][4], bf[8][2];
            #pragma unroll
            for (int im = 0; im < 4; im++) {
                const int m0 = (wm + im * 16 + g) ^ sw;
                const int m8 = (wm + im * 16 + g + 8) ^ sw;
                af[im][0] = __float_as_uint(As[cur][kr + tg    ][m0]);
                af[im][1] = __float_as_uint(As[cur][kr + tg    ][m8]);
                af[im][2] = __float_as_uint(As[cur][kr + tg + 4][m0]);
                af[im][3] = __float_as_uint(As[cur][kr + tg + 4][m8]);
            }
            #pragma unroll
            for (int in = 0; in < 8; in++) {
                const int nb = wn + in * 8 + g;
                bf[in][0] = __float_as_uint(Bs[cur][kr + tg    ][nb]);
                bf[in][1] = __float_as_uint(Bs[cur][kr + tg + 4][nb]);
            }
            #pragma unroll
            for (int im = 0; im < 4; im++)
                #pragma unroll
                for (int in = 0; in < 8; in++)
                    mma_tf32(c[im][in], af[im], bf[in]);
        }
    }

    #pragma unroll
    for (int im = 0; im < 4; im++) {
        const long row = bm + wm + im * 16 + g;
        #pragma unroll
        for (int in = 0; in < 8; in++) {
            const int col = bn + wn + in * 8 + 2 * tg;
            float* Cp = C + row * N + col;
            *(float2*)Cp           = make_float2(c[im][in][0], c[im][in][1]);
            *(float2*)(Cp + 8 * N) = make_float2(c[im][in][2], c[im][in][3]);
        }
    }
}

// ---- fused per-layer epilogue: T = sum_i xi@Wi ; h = Sn@T + b ; LN ; ReLU ---
#define EPI_TILE (64 * 68)
#define EPI_SMEM (4 * EPI_TILE * 4)          // 69632 bytes

__global__ __launch_bounds__(256)
void layer_epilogue(const float* __restrict__ x0, const float* __restrict__ x1,
                    const float* __restrict__ x2, const float* __restrict__ x3,
                    const float* __restrict__ Wl,       // (4,64,64)
                    const float* __restrict__ Sn,       // (64,64)
                    const float* __restrict__ bconv_l,  // (4,64)
                    const float* __restrict__ gamma_l,  // (64,64)
                    const float* __restrict__ beta_l,   // (64,64)
                    float* __restrict__ Xout) {
    extern __shared__ float esm[];
    float (*Xs)[68]  = (float (*)[68])(esm);
    float (*Ws)[68]  = (float (*)[68])(esm + EPI_TILE);
    float (*Ts)[68]  = (float (*)[68])(esm + 2 * EPI_TILE);
    float (*Sns)[68] = (float (*)[68])(esm + 3 * EPI_TILE);
    __shared__ float red[8];
    __shared__ float s_mu, s_rstd;

    const int n = blockIdx.x;
    const int t = threadIdx.x;
    const int u = t >> 2;
    const int q = t & 3;
    const long base = (long)n * FDIM;

    #pragma unroll
    for (int i = 0; i < 16; i++) {
        int idx = t + i * 256;
        Sns[idx >> 6][idx & 63] = Sn[idx];
    }

    unsigned long long acc[4][2];
    #pragma unroll
    for (int v = 0; v < 4; v++) { acc[v][0] = 0ull; acc[v][1] = 0ull; }

    const float* xp[4] = { x0 + base, x1 + base, x2 + base, x3 + base };

    for (int i = 0; i < 4; i++) {
        __syncthreads();
        const float* xg = xp[i];
        const float* wg = Wl + i * 4096;
        #pragma unroll
        for (int r = 0; r < 16; r++) {
            int idx = t + r * 256;
            Xs[idx >> 6][idx & 63] = xg[idx];
            Ws[idx >> 6][idx & 63] = wg[idx];
        }
        __syncthreads();
        #pragma unroll 8
        for (int k = 0; k < 64; k++) {
            unsigned long long xv = pack2(Xs[u][k]);
            #pragma unroll
            for (int v = 0; v < 4; v++) {
                ulonglong2 w = *(const ulonglong2*)&Ws[k][q * 4 + 16 * v];
                fma2(acc[v][0], xv, w.x);
                fma2(acc[v][1], xv, w.y);
            }
        }
    }

    #pragma unroll
    for (int v = 0; v < 4; v++) {
        float2 a0 = unpack2(acc[v][0]);
        float2 a1 = unpack2(acc[v][1]);
        *(float4*)&Ts[u][q * 4 + 16 * v] = make_float4(a0.x, a0.y, a1.x, a1.y);
    }
    __syncthreads();

    unsigned long long h2[4][2];
    #pragma unroll
    for (int v = 0; v < 4; v++)
        #pragma unroll
        for (int jj = 0; jj < 2; jj++) {
            int c = q * 4 + 16 * v + 2 * jj;
            float b0 = bconv_l[c]       + bconv_l[64 + c]
                     + bconv_l[128 + c] + bconv_l[192 + c];
            float b1 = bconv_l[c + 1]     + bconv_l[64 + c + 1]
                     + bconv_l[128 + c + 1] + bconv_l[192 + c + 1];
            h2[v][jj] = pack2f(b0, b1);
        }
    #pragma unroll 8
    for (int k = 0; k < 64; k++) {
        unsigned long long sv = pack2(Sns[u][k]);
        #pragma unroll
        for (int v = 0; v < 4; v++) {
            ulonglong2 w = *(const ulonglong2*)&Ts[k][q * 4 + 16 * v];
            fma2(h2[v][0], sv, w.x);
            fma2(h2[v][1], sv, w.y);
        }
    }

    float h[16];
    #pragma unroll
    for (int v = 0; v < 4; v++) {
        float2 a0 = unpack2(h2[v][0]);
        float2 a1 = unpack2(h2[v][1]);
        h[4 * v + 0] = a0.x; h[4 * v + 1] = a0.y;
        h[4 * v + 2] = a1.x; h[4 * v + 3] = a1.y;
    }

    const int lane = t & 31, wid = t >> 5;
    float lsum = 0.0f;
    #pragma unroll
    for (int j = 0; j < 16; j++) lsum += h[j];
    #pragma unroll
    for (int o = 16; o > 0; o >>= 1) lsum += __shfl_xor_sync(0xffffffffu, lsum, o);
    if (lane == 0) red[wid] = lsum;
    __syncthreads();
    if (t == 0) {
        float s = 0.0f;
        #pragma unroll
        for (int i = 0; i < 8; i++) s += red[i];
        s_mu = s * (1.0f / 4096.0f);
    }
    __syncthreads();
    const float mu = s_mu;

    float lv = 0.0f;
    #pragma unroll
    for (int j = 0; j < 16; j++) { float d = h[j] - mu; lv += d * d; }
    #pragma unroll
    for (int o = 16; o > 0; o >>= 1) lv += __shfl_xor_sync(0xffffffffu, lv, o);
    if (lane == 0) red[wid] = lv;
    __syncthreads();
    if (t == 0) {
        float s = 0.0f;
        #pragma unroll
        for (int i = 0; i < 8; i++) s += red[i];
        s_rstd = rsqrtf(s * (1.0f / 4096.0f) + LN_EPS);
    }
    __syncthreads();
    const float rstd = s_rstd;

    #pragma unroll
    for (int v = 0; v < 4; v++) {
        const int c = q * 4 + 16 * v;
        const float4 g4 = *(const float4*)(gamma_l + u * 64 + c);
        const float4 b4 = *(const float4*)(beta_l  + u * 64 + c);
        float4 o;
        o.x = fmaxf((h[4 * v + 0] - mu) * rstd * g4.x + b4.x, 0.0f);
        o.y = fmaxf((h[4 * v + 1] - mu) * rstd * g4.y + b4.y, 0.0f);
        o.z = fmaxf((h[4 * v + 2] - mu) * rstd * g4.z + b4.z, 0.0f);
        o.w = fmaxf((h[4 * v + 3] - mu) * rstd * g4.w + b4.w, 0.0f);
        *(float4*)(Xout + base + u * 64 + c) = o;
    }
}

// ----------- readout: out(2048,64) = X(2048,4096) @ Wl(4096,64) + bl --------
__global__ __launch_bounds__(256)
void final_gemm(const float* __restrict__ X, const float* __restrict__ Wl,
                const float* __restrict__ bl, float* __restrict__ out) {
    __shared__ float Xs[16][128];
    __shared__ float Ws[128][68];
    const int t = threadIdx.x;
    const long m0 = (long)blockIdx.x * 16;
    const int r  = t >> 4;
    const int cq = (t & 15) * 4;

    float acc[4] = {0.f, 0.f, 0.f, 0.f};

    for (int k0 = 0; k0 < FDIM; k0 += 128) {
        #pragma unroll
        for (int i = 0; i < 2; i++) {
            int idx = t + i * 256;
            int rr = idx >> 5, cc = (idx & 31) * 4;
            *(float4*)&Xs[rr][cc] = *(const float4*)(X + (m0 + rr) * FDIM + k0 + cc);
        }
        #pragma unroll
        for (int i = 0; i < 8; i++) {
            int idx = t + i * 256;
            int kk = idx >> 4, cc = (idx & 15) * 4;
            float4 v = *(const float4*)(Wl + (long)(k0 + kk) * 64 + cc);
            Ws[kk][cc] = v.x; Ws[kk][cc + 1] = v.y; Ws[kk][cc + 2] = v.z; Ws[kk][cc + 3] = v.w;
        }
        __syncthreads();
        #pragma unroll 16
        for (int kk = 0; kk < 128; kk++) {
            float xv = Xs[r][kk];
            #pragma unroll
            for (int j = 0; j < 4; j++) acc[j] += xv * Ws[kk][cq + j];
        }
        __syncthreads();
    }
    float4 v = make_float4(acc[0] + bl[cq], acc[1] + bl[cq + 1],
                           acc[2] + bl[cq + 2], acc[3] + bl[cq + 3]);
    *(float4*)(out + (m0 + r) * 64 + cq) = v;
}

// ---------------------------------------------------------------------------
extern "C" void kernel_launch(void* const* d_in, const int* in_sizes, int n_in,
                              void* d_out, int out_size) {
    const float* x_in    = (const float*)d_in[0];   // (2048,64,64)
    const int*   sub_adj = (const int*)  d_in[1];   // (64,64)
    const int*   adj     = (const int*)  d_in[2];   // (2048,2048)
    const float* W_convs = (const float*)d_in[3];   // (3,4,64,64)
    const float* b_convs = (const float*)d_in[4];   // (3,4,64)
    const float* ln_g    = (const float*)d_in[5];   // (3,64,64)
    const float* ln_b    = (const float*)d_in[6];   // (3,64,64)
    const float* W_lin   = (const float*)d_in[7];   // (4096,64)
    const float* b_lin   = (const float*)d_in[8];   // (64)
    float* out = (float*)d_out;

    float *Af, *AT, *A2, *A3, *X, *B1, *B2, *B3, *Sn;
    cudaGetSymbolAddress((void**)&Af, g_Af);
    cudaGetSymbolAddress((void**)&AT, g_AT);
    cudaGetSymbolAddress((void**)&A2, g_A2);
    cudaGetSymbolAddress((void**)&A3, g_A3);
    cudaGetSymbolAddress((void**)&X,  g_X);
    cudaGetSymbolAddress((void**)&B1, g_B1);
    cudaGetSymbolAddress((void**)&B2, g_B2);
    cudaGetSymbolAddress((void**)&B3, g_B3);
    cudaGetSymbolAddress((void**)&Sn, g_Sn);

    cudaFuncSetAttribute(gemm_tt, cudaFuncAttributeMaxDynamicSharedMemorySize,
                         GEMM_SMEM);
    cudaFuncSetAttribute(layer_epilogue,
                         cudaFuncAttributeMaxDynamicSharedMemorySize, EPI_SMEM);

    // precompute: Af, AfT, (A^2)^T, (A^3)^T (all exact integer GEMMs), Sn
    cast_i2f<<<(NN * NN) / 256, 256>>>(adj, Af);
    cast_i2f_T<<<dim3(NN / 32, NN / 32), dim3(32, 8)>>>(adj, AT);
    gemm_tt<<<dim3(NN / 128, NN / 128), 128, GEMM_SMEM>>>(Af, AT, A2, NN, NN, NN);
    gemm_tt<<<dim3(NN / 128, NN / 128), 128, GEMM_SMEM>>>(Af, A2, A3, NN, NN, NN);
    compute_sn<<<1, 64>>>(sub_adj, Sn);

    const dim3 gmeta(FDIM / 128, NN / 128);
    for (int l = 0; l < 3; l++) {
        const float* curX = (l == 0) ? x_in : X;
        const float* Wl = W_convs + (long)l * 4 * 4096;

        // x1 = A @ x ; x2 = A^2 @ x1 ; x3 = A^3 @ x2
        gemm_tt<<<gmeta, 128, GEMM_SMEM>>>(AT, curX, B1, NN, FDIM, NN);
        gemm_tt<<<gmeta, 128, GEMM_SMEM>>>(A2, B1,  B2, NN, FDIM, NN);
        gemm_tt<<<gmeta, 128, GEMM_SMEM>>>(A3, B2,  B3, NN, FDIM, NN);

        // X = relu(LN(Sn @ (sum_i xi Wi) + sum_i b_i))
        layer_epilogue<<<NN, 256, EPI_SMEM>>>(curX, B1, B2, B3, Wl, Sn,
                                              b_convs + (long)l * 256,
                                              ln_g + (long)l * 4096,
                                              ln_b + (long)l * 4096,
                                              X);
    }

    final_gemm<<<NN / 16, 256>>>(X, W_lin, b_lin, out);
}

// round 11
// speedup vs baseline: 3.1812x; 1.0029x over previous
#include <cuda_runtime.h>
#include <cstdint>

// Problem constants
#define NN    2048          // meta nodes
#define MDIM  64            // subgraph nodes
#define DDIM  64            // channels
#define FDIM  4096          // MDIM*DDIM
#define OUTD  64
#define LN_EPS 1e-5f

// ------------------------- scratch (device globals; no allocation) ----------
__device__ float g_Af[NN * NN];     // A (row-major)
__device__ float g_AT[NN * NN];     // A^T
__device__ float g_A2[NN * NN];     // (A^2)^T
__device__ float g_A3[NN * NN];     // (A^3)^T
__device__ float g_X [NN * FDIM];
__device__ float g_B1[NN * FDIM];
__device__ float g_B2[NN * FDIM];
__device__ float g_B3[NN * FDIM];
__device__ float g_Sn[MDIM * MDIM];

// ------------------------- int32 -> float cast ------------------------------
__global__ void cast_i2f(const int* __restrict__ a, float* __restrict__ o) {
    int i = blockIdx.x * blockDim.x + threadIdx.x;
    o[i] = (float)a[i];
}

// transpose-cast: oT[j,i] = (float)a[i,j], 32x32 smem tiles
__global__ void cast_i2f_T(const int* __restrict__ a, float* __restrict__ oT) {
    __shared__ float tile[32][33];
    int bx = blockIdx.x * 32, by = blockIdx.y * 32;
    int tx = threadIdx.x, ty = threadIdx.y;            // 32x8
    #pragma unroll
    for (int j = 0; j < 32; j += 8)
        tile[ty + j][tx] = (float)a[(long)(by + ty + j) * NN + bx + tx];
    __syncthreads();
    #pragma unroll
    for (int j = 0; j < 32; j += 8)
        oT[(long)(bx + ty + j) * NN + by + tx] = tile[tx][ty + j];
}

// ------------------------- Sn = D^-1/2 (S+I) D^-1/2 -------------------------
__global__ void compute_sn(const int* __restrict__ sub_adj, float* __restrict__ Sn) {
    __shared__ float dinv[MDIM];
    int u = threadIdx.x;
    float s = 1.0f;
    for (int v = 0; v < MDIM; v++) s += (float)sub_adj[u * MDIM + v];
    dinv[u] = rsqrtf(s);
    __syncthreads();
    float du = dinv[u];
    for (int v = 0; v < MDIM; v++) {
        float a = (float)sub_adj[u * MDIM + v] + (u == v ? 1.0f : 0.0f);
        Sn[u * MDIM + v] = du * a * dinv[v];
    }
}

// ------------------------- mma / cp.async / f32x2 helpers --------------------
__device__ __forceinline__ void mma_tf32(float c[4], const uint32_t a[4],
                                         const uint32_t b[2]) {
    asm volatile(
        "mma.sync.aligned.m16n8k8.row.col.f32.tf32.tf32.f32 "
        "{%0,%1,%2,%3}, {%4,%5,%6,%7}, {%8,%9}, {%0,%1,%2,%3};\n"
        : "+f"(c[0]), "+f"(c[1]), "+f"(c[2]), "+f"(c[3])
        : "r"(a[0]), "r"(a[1]), "r"(a[2]), "r"(a[3]), "r"(b[0]), "r"(b[1]));
}

__device__ __forceinline__ void cp16(float* smem, const float* gmem) {
    uint32_t s = (uint32_t)__cvta_generic_to_shared(smem);
    asm volatile("cp.async.cg.shared.global [%0], [%1], 16;\n" :: "r"(s), "l"(gmem));
}
__device__ __forceinline__ void cp_commit() {
    asm volatile("cp.async.commit_group;\n");
}
template<int W> __device__ __forceinline__ void cp_wait() {
    asm volatile("cp.async.wait_group %0;\n" :: "n"(W));
}

__device__ __forceinline__ unsigned long long pack2(float x) {
    unsigned long long r;
    asm("mov.b64 %0, {%1, %1};" : "=l"(r) : "f"(x));
    return r;
}
__device__ __forceinline__ unsigned long long pack2f(float lo, float hi) {
    unsigned long long r;
    asm("mov.b64 %0, {%1, %2};" : "=l"(r) : "f"(lo), "f"(hi));
    return r;
}
__device__ __forceinline__ void fma2(unsigned long long& d, unsigned long long a,
                                     unsigned long long b) {
    asm("fma.rn.f32x2 %0, %1, %2, %0;" : "+l"(d) : "l"(a), "l"(b));
}
__device__ __forceinline__ float2 unpack2(unsigned long long v) {
    float2 f;
    asm("mov.b64 {%0, %1}, %2;" : "=f"(f.x), "=f"(f.y) : "l"(v));
    return f;
}

// ---------------- tensor-core GEMM: C(MxN) = (AT)^T (MxK) * B(KxN) ----------
// fp32 in/out, tf32 mma (raw fp32 bits => truncation; exact for integer A).
// CTA tile 256x128x32, 256 threads (8 warps, 4x2 grid), warp tile 64x64.
// 4-stage cp.async pipeline, 1 CTA/SM. AT is the K x M transpose of the left
// operand. cp.async issue count per tile: (256+128) rows * 8 chunks = 3072.
#define TBM 256
#define TBN 128
#define TBK 32
#define STAGES 4
#define ASPAD 264
#define BSPAD 136
#define GEMM_SMEM (STAGES * TBK * (ASPAD + BSPAD) * 4)   // 204800 bytes

__global__ __launch_bounds__(256, 1)
void gemm_tt(const float* __restrict__ AT, const float* __restrict__ B,
             float* __restrict__ C, int M, int N, int K) {
    extern __shared__ float sm[];
    float (*As)[TBK][ASPAD] = (float (*)[TBK][ASPAD])sm;
    float (*Bs)[TBK][BSPAD] = (float (*)[TBK][BSPAD])(sm + STAGES * TBK * ASPAD);

    const int t  = threadIdx.x;               // 0..255
    const long bm = (long)blockIdx.y * TBM;
    const long bn = (long)blockIdx.x * TBN;
    const int lane = t & 31;
    const int g  = lane >> 2;                 // 0..7
    const int tg = lane & 3;                  // 0..3
    const int w  = t >> 5;                    // 0..7
    const int wm = (w >> 1) * 64;             // 0,64,128,192
    const int wn = (w & 1) * 64;              // 0 or 64

    // A^T staging: k-row = t>>3 (0..31), 8 x 16B chunks along m (0..255)
    const int akk = t >> 3;
    const int ac0 = (t & 7) * 4;
    const int asw = ((akk >> 4) & 1) << 4;    // XOR-16 swizzle keyed on k bit 4
    const float* Ag = AT + (long)akk * M + bm;
    // B staging: k-rows bkk+8j (j=0..3), one 16B chunk along n
    const int bkk = t >> 5;                   // 0..7
    const int bn4 = (t & 31) * 4;
    const float* Bg = B + (long)bkk * N + bn + bn4;

    float c[4][8][4];
    #pragma unroll
    for (int im = 0; im < 4; im++)
        #pragma unroll
        for (int in = 0; in < 8; in++) {
            c[im][in][0] = 0.f; c[im][in][1] = 0.f;
            c[im][in][2] = 0.f; c[im][in][3] = 0.f;
        }

    const int ktiles = K / TBK;

    // prologue: issue first STAGES-1 tiles
    #pragma unroll
    for (int s = 0; s < STAGES - 1; s++) {
        const long k0 = (long)s * TBK;
        #pragma unroll
        for (int j = 0; j < 8; j++)
            cp16(&As[s][akk][(ac0 + 32 * j) ^ asw], Ag + k0 * M + ac0 + 32 * j);
        #pragma unroll
        for (int j = 0; j < 4; j++)
            cp16(&Bs[s][bkk + 8 * j][bn4], Bg + (k0 + 8 * j) * N);
        cp_commit();
    }

    for (int i = 0; i < ktiles; i++) {
        if (i + STAGES - 1 < ktiles) cp_wait<STAGES - 2>(); else cp_wait<0>();
        __syncthreads();

        // issue tile i+STAGES-1 into the slot freed at iteration i-1
        const int nx = i + STAGES - 1;
        if (nx < ktiles) {
            const int st = nx & (STAGES - 1);
            const long k0 = (long)nx * TBK;
            #pragma unroll
            for (int j = 0; j < 8; j++)
                cp16(&As[st][akk][(ac0 + 32 * j) ^ asw], Ag + k0 * M + ac0 + 32 * j);
            #pragma unroll
            for (int j = 0; j < 4; j++)
                cp16(&Bs[st][bkk + 8 * j][bn4], Bg + (k0 + 8 * j) * N);
            cp_commit();
        }

        const int cur = i & (STAGES - 1);
        #pragma unroll
        for (int ks = 0; ks < 4; ks++) {
            const int kr = ks * 8;
            const int sw = (ks >> 1) << 4;
            uint32_t af[4][4], bf[8][2];
            #pragma unroll
            for (int im = 0; im < 4; im++) {
                const int m0 = (wm + im * 16 + g) ^ sw;
                const int m8 = (wm + im * 16 + g + 8) ^ sw;
                af[im][0] = __float_as_uint(As[cur][kr + tg    ][m0]);
                af[im][1] = __float_as_uint(As[cur][kr + tg    ][m8]);
                af[im][2] = __float_as_uint(As[cur][kr + tg + 4][m0]);
                af[im][3] = __float_as_uint(As[cur][kr + tg + 4][m8]);
            }
            #pragma unroll
            for (int in = 0; in < 8; in++) {
                const int nb = wn + in * 8 + g;
                bf[in][0] = __float_as_uint(Bs[cur][kr + tg    ][nb]);
                bf[in][1] = __float_as_uint(Bs[cur][kr + tg + 4][nb]);
            }
            #pragma unroll
            for (int im = 0; im < 4; im++)
                #pragma unroll
                for (int in = 0; in < 8; in++)
                    mma_tf32(c[im][in], af[im], bf[in]);
        }
    }

    #pragma unroll
    for (int im = 0; im < 4; im++) {
        const long row = bm + wm + im * 16 + g;
        #pragma unroll
        for (int in = 0; in < 8; in++) {
            const int col = bn + wn + in * 8 + 2 * tg;
            float* Cp = C + row * N + col;
            *(float2*)Cp           = make_float2(c[im][in][0], c[im][in][1]);
            *(float2*)(Cp + 8 * N) = make_float2(c[im][in][2], c[im][in][3]);
        }
    }
}

// ---- fused per-layer epilogue: T = sum_i xi@Wi ; h = Sn@T + b ; LN ; ReLU ---
#define EPI_TILE (64 * 68)
#define EPI_SMEM (4 * EPI_TILE * 4)          // 69632 bytes

__global__ __launch_bounds__(256)
void layer_epilogue(const float* __restrict__ x0, const float* __restrict__ x1,
                    const float* __restrict__ x2, const float* __restrict__ x3,
                    const float* __restrict__ Wl,       // (4,64,64)
                    const float* __restrict__ Sn,       // (64,64)
                    const float* __restrict__ bconv_l,  // (4,64)
                    const float* __restrict__ gamma_l,  // (64,64)
                    const float* __restrict__ beta_l,   // (64,64)
                    float* __restrict__ Xout) {
    extern __shared__ float esm[];
    float (*Xs)[68]  = (float (*)[68])(esm);
    float (*Ws)[68]  = (float (*)[68])(esm + EPI_TILE);
    float (*Ts)[68]  = (float (*)[68])(esm + 2 * EPI_TILE);
    float (*Sns)[68] = (float (*)[68])(esm + 3 * EPI_TILE);
    __shared__ float red[8];
    __shared__ float s_mu, s_rstd;

    const int n = blockIdx.x;
    const int t = threadIdx.x;
    const int u = t >> 2;
    const int q = t & 3;
    const long base = (long)n * FDIM;

    #pragma unroll
    for (int i = 0; i < 16; i++) {
        int idx = t + i * 256;
        Sns[idx >> 6][idx & 63] = Sn[idx];
    }

    unsigned long long acc[4][2];
    #pragma unroll
    for (int v = 0; v < 4; v++) { acc[v][0] = 0ull; acc[v][1] = 0ull; }

    const float* xp[4] = { x0 + base, x1 + base, x2 + base, x3 + base };

    for (int i = 0; i < 4; i++) {
        __syncthreads();
        const float* xg = xp[i];
        const float* wg = Wl + i * 4096;
        #pragma unroll
        for (int r = 0; r < 16; r++) {
            int idx = t + r * 256;
            Xs[idx >> 6][idx & 63] = xg[idx];
            Ws[idx >> 6][idx & 63] = wg[idx];
        }
        __syncthreads();
        #pragma unroll 8
        for (int k = 0; k < 64; k++) {
            unsigned long long xv = pack2(Xs[u][k]);
            #pragma unroll
            for (int v = 0; v < 4; v++) {
                ulonglong2 w = *(const ulonglong2*)&Ws[k][q * 4 + 16 * v];
                fma2(acc[v][0], xv, w.x);
                fma2(acc[v][1], xv, w.y);
            }
        }
    }

    #pragma unroll
    for (int v = 0; v < 4; v++) {
        float2 a0 = unpack2(acc[v][0]);
        float2 a1 = unpack2(acc[v][1]);
        *(float4*)&Ts[u][q * 4 + 16 * v] = make_float4(a0.x, a0.y, a1.x, a1.y);
    }
    __syncthreads();

    unsigned long long h2[4][2];
    #pragma unroll
    for (int v = 0; v < 4; v++)
        #pragma unroll
        for (int jj = 0; jj < 2; jj++) {
            int c = q * 4 + 16 * v + 2 * jj;
            float b0 = bconv_l[c]       + bconv_l[64 + c]
                     + bconv_l[128 + c] + bconv_l[192 + c];
            float b1 = bconv_l[c + 1]     + bconv_l[64 + c + 1]
                     + bconv_l[128 + c + 1] + bconv_l[192 + c + 1];
            h2[v][jj] = pack2f(b0, b1);
        }
    #pragma unroll 8
    for (int k = 0; k < 64; k++) {
        unsigned long long sv = pack2(Sns[u][k]);
        #pragma unroll
        for (int v = 0; v < 4; v++) {
            ulonglong2 w = *(const ulonglong2*)&Ts[k][q * 4 + 16 * v];
            fma2(h2[v][0], sv, w.x);
            fma2(h2[v][1], sv, w.y);
        }
    }

    float h[16];
    #pragma unroll
    for (int v = 0; v < 4; v++) {
        float2 a0 = unpack2(h2[v][0]);
        float2 a1 = unpack2(h2[v][1]);
        h[4 * v + 0] = a0.x; h[4 * v + 1] = a0.y;
        h[4 * v + 2] = a1.x; h[4 * v + 3] = a1.y;
    }

    const int lane = t & 31, wid = t >> 5;
    float lsum = 0.0f;
    #pragma unroll
    for (int j = 0; j < 16; j++) lsum += h[j];
    #pragma unroll
    for (int o = 16; o > 0; o >>= 1) lsum += __shfl_xor_sync(0xffffffffu, lsum, o);
    if (lane == 0) red[wid] = lsum;
    __syncthreads();
    if (t == 0) {
        float s = 0.0f;
        #pragma unroll
        for (int i = 0; i < 8; i++) s += red[i];
        s_mu = s * (1.0f / 4096.0f);
    }
    __syncthreads();
    const float mu = s_mu;

    float lv = 0.0f;
    #pragma unroll
    for (int j = 0; j < 16; j++) { float d = h[j] - mu; lv += d * d; }
    #pragma unroll
    for (int o = 16; o > 0; o >>= 1) lv += __shfl_xor_sync(0xffffffffu, lv, o);
    if (lane == 0) red[wid] = lv;
    __syncthreads();
    if (t == 0) {
        float s = 0.0f;
        #pragma unroll
        for (int i = 0; i < 8; i++) s += red[i];
        s_rstd = rsqrtf(s * (1.0f / 4096.0f) + LN_EPS);
    }
    __syncthreads();
    const float rstd = s_rstd;

    #pragma unroll
    for (int v = 0; v < 4; v++) {
        const int c = q * 4 + 16 * v;
        const float4 g4 = *(const float4*)(gamma_l + u * 64 + c);
        const float4 b4 = *(const float4*)(beta_l  + u * 64 + c);
        float4 o;
        o.x = fmaxf((h[4 * v + 0] - mu) * rstd * g4.x + b4.x, 0.0f);
        o.y = fmaxf((h[4 * v + 1] - mu) * rstd * g4.y + b4.y, 0.0f);
        o.z = fmaxf((h[4 * v + 2] - mu) * rstd * g4.z + b4.z, 0.0f);
        o.w = fmaxf((h[4 * v + 3] - mu) * rstd * g4.w + b4.w, 0.0f);
        *(float4*)(Xout + base + u * 64 + c) = o;
    }
}

// ----------- readout: out(2048,64) = X(2048,4096) @ Wl(4096,64) + bl --------
__global__ __launch_bounds__(256)
void final_gemm(const float* __restrict__ X, const float* __restrict__ Wl,
                const float* __restrict__ bl, float* __restrict__ out) {
    __shared__ float Xs[16][128];
    __shared__ float Ws[128][68];
    const int t = threadIdx.x;
    const long m0 = (long)blockIdx.x * 16;
    const int r  = t >> 4;
    const int cq = (t & 15) * 4;

    float acc[4] = {0.f, 0.f, 0.f, 0.f};

    for (int k0 = 0; k0 < FDIM; k0 += 128) {
        #pragma unroll
        for (int i = 0; i < 2; i++) {
            int idx = t + i * 256;
            int rr = idx >> 5, cc = (idx & 31) * 4;
            *(float4*)&Xs[rr][cc] = *(const float4*)(X + (m0 + rr) * FDIM + k0 + cc);
        }
        #pragma unroll
        for (int i = 0; i < 8; i++) {
            int idx = t + i * 256;
            int kk = idx >> 4, cc = (idx & 15) * 4;
            float4 v = *(const float4*)(Wl + (long)(k0 + kk) * 64 + cc);
            Ws[kk][cc] = v.x; Ws[kk][cc + 1] = v.y; Ws[kk][cc + 2] = v.z; Ws[kk][cc + 3] = v.w;
        }
        __syncthreads();
        #pragma unroll 16
        for (int kk = 0; kk < 128; kk++) {
            float xv = Xs[r][kk];
            #pragma unroll
            for (int j = 0; j < 4; j++) acc[j] += xv * Ws[kk][cq + j];
        }
        __syncthreads();
    }
    float4 v = make_float4(acc[0] + bl[cq], acc[1] + bl[cq + 1],
                           acc[2] + bl[cq + 2], acc[3] + bl[cq + 3]);
    *(float4*)(out + (m0 + r) * 64 + cq) = v;
}

// ---------------------------------------------------------------------------
extern "C" void kernel_launch(void* const* d_in, const int* in_sizes, int n_in,
                              void* d_out, int out_size) {
    const float* x_in    = (const float*)d_in[0];   // (2048,64,64)
    const int*   sub_adj = (const int*)  d_in[1];   // (64,64)
    const int*   adj     = (const int*)  d_in[2];   // (2048,2048)
    const float* W_convs = (const float*)d_in[3];   // (3,4,64,64)
    const float* b_convs = (const float*)d_in[4];   // (3,4,64)
    const float* ln_g    = (const float*)d_in[5];   // (3,64,64)
    const float* ln_b    = (const float*)d_in[6];   // (3,64,64)
    const float* W_lin   = (const float*)d_in[7];   // (4096,64)
    const float* b_lin   = (const float*)d_in[8];   // (64)
    float* out = (float*)d_out;

    float *Af, *AT, *A2, *A3, *X, *B1, *B2, *B3, *Sn;
    cudaGetSymbolAddress((void**)&Af, g_Af);
    cudaGetSymbolAddress((void**)&AT, g_AT);
    cudaGetSymbolAddress((void**)&A2, g_A2);
    cudaGetSymbolAddress((void**)&A3, g_A3);
    cudaGetSymbolAddress((void**)&X,  g_X);
    cudaGetSymbolAddress((void**)&B1, g_B1);
    cudaGetSymbolAddress((void**)&B2, g_B2);
    cudaGetSymbolAddress((void**)&B3, g_B3);
    cudaGetSymbolAddress((void**)&Sn, g_Sn);

    cudaFuncSetAttribute(gemm_tt, cudaFuncAttributeMaxDynamicSharedMemorySize,
                         GEMM_SMEM);
    cudaFuncSetAttribute(layer_epilogue,
                         cudaFuncAttributeMaxDynamicSharedMemorySize, EPI_SMEM);

    // precompute: Af, AfT, (A^2)^T, (A^3)^T (all exact integer GEMMs), Sn
    cast_i2f<<<(NN * NN) / 256, 256>>>(adj, Af);
    cast_i2f_T<<<dim3(NN / 32, NN / 32), dim3(32, 8)>>>(adj, AT);
    gemm_tt<<<dim3(NN / TBN, NN / TBM), 256, GEMM_SMEM>>>(Af, AT, A2, NN, NN, NN);
    gemm_tt<<<dim3(NN / TBN, NN / TBM), 256, GEMM_SMEM>>>(Af, A2, A3, NN, NN, NN);
    compute_sn<<<1, 64>>>(sub_adj, Sn);

    const dim3 gmeta(FDIM / TBN, NN / TBM);   // (32, 8)
    for (int l = 0; l < 3; l++) {
        const float* curX = (l == 0) ? x_in : X;
        const float* Wl = W_convs + (long)l * 4 * 4096;

        // x1 = A @ x ; x2 = A^2 @ x1 ; x3 = A^3 @ x2
        gemm_tt<<<gmeta, 256, GEMM_SMEM>>>(AT, curX, B1, NN, FDIM, NN);
        gemm_tt<<<gmeta, 256, GEMM_SMEM>>>(A2, B1,  B2, NN, FDIM, NN);
        gemm_tt<<<gmeta, 256, GEMM_SMEM>>>(A3, B2,  B3, NN, FDIM, NN);

        // X = relu(LN(Sn @ (sum_i xi Wi) + sum_i b_i))
        layer_epilogue<<<NN, 256, EPI_SMEM>>>(curX, B1, B2, B3, Wl, Sn,
                                              b_convs + (long)l * 256,
                                              ln_g + (long)l * 4096,
                                              ln_b + (long)l * 4096,
                                              X);
    }

    final_gemm<<<NN / 16, 256>>>(X, W_lin, b_lin, out);
}

// round 12
// speedup vs baseline: 3.7292x; 1.1723x over previous
#include <cuda_runtime.h>
#include <cstdint>

// Problem constants
#define NN    2048          // meta nodes
#define MDIM  64            // subgraph nodes
#define DDIM  64            // channels
#define FDIM  4096          // MDIM*DDIM
#define OUTD  64
#define LN_EPS 1e-5f

// ------------------------- scratch (device globals; no allocation) ----------
__device__ float g_Af[NN * NN];     // A (row-major)
__device__ float g_AT[NN * NN];     // A^T
__device__ float g_A2[NN * NN];     // (A^2)^T
__device__ float g_A3[NN * NN];     // (A^3)^T
__device__ float g_X [NN * FDIM];
__device__ float g_B1[NN * FDIM];
__device__ float g_B2[NN * FDIM];
__device__ float g_B3[NN * FDIM];
__device__ float g_T [NN * FDIM];   // T = sum_i xi @ Wi
__device__ float g_Sn[MDIM * MDIM];

// ------------------------- int32 -> float cast ------------------------------
__global__ void cast_i2f(const int* __restrict__ a, float* __restrict__ o) {
    int i = blockIdx.x * blockDim.x + threadIdx.x;
    o[i] = (float)a[i];
}

// transpose-cast: oT[j,i] = (float)a[i,j], 32x32 smem tiles
__global__ void cast_i2f_T(const int* __restrict__ a, float* __restrict__ oT) {
    __shared__ float tile[32][33];
    int bx = blockIdx.x * 32, by = blockIdx.y * 32;
    int tx = threadIdx.x, ty = threadIdx.y;            // 32x8
    #pragma unroll
    for (int j = 0; j < 32; j += 8)
        tile[ty + j][tx] = (float)a[(long)(by + ty + j) * NN + bx + tx];
    __syncthreads();
    #pragma unroll
    for (int j = 0; j < 32; j += 8)
        oT[(long)(bx + ty + j) * NN + by + tx] = tile[tx][ty + j];
}

// ------------------------- Sn = D^-1/2 (S+I) D^-1/2 (256 threads) -----------
__global__ void compute_sn(const int* __restrict__ sub_adj, float* __restrict__ Sn) {
    __shared__ float part[MDIM][4];
    __shared__ float dinv[MDIM];
    const int t = threadIdx.x;           // 256
    const int u = t >> 2, q = t & 3;
    float s = 0.0f;
    #pragma unroll
    for (int v = 0; v < 16; v++) s += (float)sub_adj[u * MDIM + q * 16 + v];
    part[u][q] = s;
    __syncthreads();
    if (q == 0)
        dinv[u] = rsqrtf(1.0f + part[u][0] + part[u][1] + part[u][2] + part[u][3]);
    __syncthreads();
    #pragma unroll
    for (int j = 0; j < 16; j++) {
        int idx = t + j * 256;           // 0..4095
        int uu = idx >> 6, vv = idx & 63;
        float a = (float)sub_adj[idx] + (uu == vv ? 1.0f : 0.0f);
        Sn[idx] = dinv[uu] * a * dinv[vv];
    }
}

// ------------------------- mma / cp.async / f32x2 helpers --------------------
__device__ __forceinline__ void mma_tf32(float c[4], const uint32_t a[4],
                                         const uint32_t b[2]) {
    asm volatile(
        "mma.sync.aligned.m16n8k8.row.col.f32.tf32.tf32.f32 "
        "{%0,%1,%2,%3}, {%4,%5,%6,%7}, {%8,%9}, {%0,%1,%2,%3};\n"
        : "+f"(c[0]), "+f"(c[1]), "+f"(c[2]), "+f"(c[3])
        : "r"(a[0]), "r"(a[1]), "r"(a[2]), "r"(a[3]), "r"(b[0]), "r"(b[1]));
}

__device__ __forceinline__ void cp16(float* smem, const float* gmem) {
    uint32_t s = (uint32_t)__cvta_generic_to_shared(smem);
    asm volatile("cp.async.cg.shared.global [%0], [%1], 16;\n" :: "r"(s), "l"(gmem));
}
__device__ __forceinline__ void cp_commit() {
    asm volatile("cp.async.commit_group;\n");
}
template<int W> __device__ __forceinline__ void cp_wait() {
    asm volatile("cp.async.wait_group %0;\n" :: "n"(W));
}

__device__ __forceinline__ unsigned long long pack2(float x) {
    unsigned long long r;
    asm("mov.b64 %0, {%1, %1};" : "=l"(r) : "f"(x));
    return r;
}
__device__ __forceinline__ unsigned long long pack2f(float lo, float hi) {
    unsigned long long r;
    asm("mov.b64 %0, {%1, %2};" : "=l"(r) : "f"(lo), "f"(hi));
    return r;
}
__device__ __forceinline__ void fma2(unsigned long long& d, unsigned long long a,
                                     unsigned long long b) {
    asm("fma.rn.f32x2 %0, %1, %2, %0;" : "+l"(d) : "l"(a), "l"(b));
}
__device__ __forceinline__ float2 unpack2(unsigned long long v) {
    float2 f;
    asm("mov.b64 {%0, %1}, %2;" : "=f"(f.x), "=f"(f.y) : "l"(v));
    return f;
}

__device__ __forceinline__ float tf32_hi(float x) {
    return __uint_as_float(__float_as_uint(x) & 0xFFFFE000u);
}

// ---------------- tensor-core GEMM: C(MxN) = (AT)^T (MxK) * B(KxN) ----------
// (unchanged from R11) CTA 256x128x32, 256 threads, warp tile 64x64, 4 stages.
#define TBM 256
#define TBN 128
#define TBK 32
#define STAGES 4
#define ASPAD 264
#define BSPAD 136
#define GEMM_SMEM (STAGES * TBK * (ASPAD + BSPAD) * 4)   // 204800 bytes

__global__ __launch_bounds__(256, 1)
void gemm_tt(const float* __restrict__ AT, const float* __restrict__ B,
             float* __restrict__ C, int M, int N, int K) {
    extern __shared__ float sm[];
    float (*As)[TBK][ASPAD] = (float (*)[TBK][ASPAD])sm;
    float (*Bs)[TBK][BSPAD] = (float (*)[TBK][BSPAD])(sm + STAGES * TBK * ASPAD);

    const int t  = threadIdx.x;               // 0..255
    const long bm = (long)blockIdx.y * TBM;
    const long bn = (long)blockIdx.x * TBN;
    const int lane = t & 31;
    const int g  = lane >> 2;                 // 0..7
    const int tg = lane & 3;                  // 0..3
    const int w  = t >> 5;                    // 0..7
    const int wm = (w >> 1) * 64;             // 0,64,128,192
    const int wn = (w & 1) * 64;              // 0 or 64

    const int akk = t >> 3;
    const int ac0 = (t & 7) * 4;
    const int asw = ((akk >> 4) & 1) << 4;
    const float* Ag = AT + (long)akk * M + bm;
    const int bkk = t >> 5;
    const int bn4 = (t & 31) * 4;
    const float* Bg = B + (long)bkk * N + bn + bn4;

    float c[4][8][4];
    #pragma unroll
    for (int im = 0; im < 4; im++)
        #pragma unroll
        for (int in = 0; in < 8; in++) {
            c[im][in][0] = 0.f; c[im][in][1] = 0.f;
            c[im][in][2] = 0.f; c[im][in][3] = 0.f;
        }

    const int ktiles = K / TBK;

    #pragma unroll
    for (int s = 0; s < STAGES - 1; s++) {
        const long k0 = (long)s * TBK;
        #pragma unroll
        for (int j = 0; j < 8; j++)
            cp16(&As[s][akk][(ac0 + 32 * j) ^ asw], Ag + k0 * M + ac0 + 32 * j);
        #pragma unroll
        for (int j = 0; j < 4; j++)
            cp16(&Bs[s][bkk + 8 * j][bn4], Bg + (k0 + 8 * j) * N);
        cp_commit();
    }

    for (int i = 0; i < ktiles; i++) {
        if (i + STAGES - 1 < ktiles) cp_wait<STAGES - 2>(); else cp_wait<0>();
        __syncthreads();

        const int nx = i + STAGES - 1;
        if (nx < ktiles) {
            const int st = nx & (STAGES - 1);
            const long k0 = (long)nx * TBK;
            #pragma unroll
            for (int j = 0; j < 8; j++)
                cp16(&As[st][akk][(ac0 + 32 * j) ^ asw], Ag + k0 * M + ac0 + 32 * j);
            #pragma unroll
            for (int j = 0; j < 4; j++)
                cp16(&Bs[st][bkk + 8 * j][bn4], Bg + (k0 + 8 * j) * N);
            cp_commit();
        }

        const int cur = i & (STAGES - 1);
        #pragma unroll
        for (int ks = 0; ks < 4; ks++) {
            const int kr = ks * 8;
            const int sw = (ks >> 1) << 4;
            uint32_t af[4][4], bf[8][2];
            #pragma unroll
            for (int im = 0; im < 4; im++) {
                const int m0 = (wm + im * 16 + g) ^ sw;
                const int m8 = (wm + im * 16 + g + 8) ^ sw;
                af[im][0] = __float_as_uint(As[cur][kr + tg    ][m0]);
                af[im][1] = __float_as_uint(As[cur][kr + tg    ][m8]);
                af[im][2] = __float_as_uint(As[cur][kr + tg + 4][m0]);
                af[im][3] = __float_as_uint(As[cur][kr + tg + 4][m8]);
            }
            #pragma unroll
            for (int in = 0; in < 8; in++) {
                const int nb = wn + in * 8 + g;
                bf[in][0] = __float_as_uint(Bs[cur][kr + tg    ][nb]);
                bf[in][1] = __float_as_uint(Bs[cur][kr + tg + 4][nb]);
            }
            #pragma unroll
            for (int im = 0; im < 4; im++)
                #pragma unroll
                for (int in = 0; in < 8; in++)
                    mma_tf32(c[im][in], af[im], bf[in]);
        }
    }

    #pragma unroll
    for (int im = 0; im < 4; im++) {
        const long row = bm + wm + im * 16 + g;
        #pragma unroll
        for (int in = 0; in < 8; in++) {
            const int col = bn + wn + in * 8 + 2 * tg;
            float* Cp = C + row * N + col;
            *(float2*)Cp           = make_float2(c[im][in][0], c[im][in][1]);
            *(float2*)(Cp + 8 * N) = make_float2(c[im][in][2], c[im][in][3]);
        }
    }
}

// ============ wsum: T(131072x64) = sum_i Xi(131072x64) @ Wi(64x64) ===========
// Tensor-core, 3-pass split-tf32 (xh*Wh + xl*Wh + xh*Wl) => ~fp32 accuracy.
// CTA: 256 rows x 64 cols, 256 threads (8 warps, 4x2), warp tile 64x32.
// X staged row-major (coalesced), W is naturally k-major. Pad 68 => all
// fragment LDS conflict-free (bank = 4g+tg / 4tg+g patterns).
#define WSU_XT (256 * 68)
#define WSU_WT (64 * 68)
#define WSU_SMEM ((2 * WSU_XT + 2 * WSU_WT) * 4)   // 174080 bytes

__global__ __launch_bounds__(256, 1)
void wsum(const float* __restrict__ x0, const float* __restrict__ x1,
          const float* __restrict__ x2, const float* __restrict__ x3,
          const float* __restrict__ Wl,   // (4,64,64)
          float* __restrict__ T) {
    extern __shared__ float wsm[];
    float (*Xh)[68]  = (float (*)[68])(wsm);
    float (*Xl)[68]  = (float (*)[68])(wsm + WSU_XT);
    float (*Wh)[68]  = (float (*)[68])(wsm + 2 * WSU_XT);
    float (*Wlo)[68] = (float (*)[68])(wsm + 2 * WSU_XT + WSU_WT);

    const int t = threadIdx.x;
    const long r0 = (long)blockIdx.x * 256;
    const int lane = t & 31;
    const int g  = lane >> 2;        // 0..7
    const int tg = lane & 3;         // 0..3
    const int w  = t >> 5;
    const int wr = w >> 1;           // 0..3 : 64-row group
    const int wc = w & 1;            // 0..1 : 32-col group

    float c[4][4][4];
    #pragma unroll
    for (int im = 0; im < 4; im++)
        #pragma unroll
        for (int in = 0; in < 4; in++) {
            c[im][in][0] = 0.f; c[im][in][1] = 0.f;
            c[im][in][2] = 0.f; c[im][in][3] = 0.f;
        }

    const float* xs[4] = { x0, x1, x2, x3 };

    #pragma unroll
    for (int s = 0; s < 4; s++) {
        __syncthreads();                 // smem reuse guard
        // stage X (256 rows x 64), split into hi/lo
        #pragma unroll
        for (int j = 0; j < 16; j++) {
            int idx = t + 256 * j;       // float4 index, 4096 total
            int row = idx >> 4, c4 = (idx & 15) * 4;
            float4 v = *(const float4*)(xs[s] + (r0 + row) * 64 + c4);
            float4 h, l;
            h.x = tf32_hi(v.x); l.x = v.x - h.x;
            h.y = tf32_hi(v.y); l.y = v.y - h.y;
            h.z = tf32_hi(v.z); l.z = v.z - h.z;
            h.w = tf32_hi(v.w); l.w = v.w - h.w;
            *(float4*)&Xh[row][c4] = h;
            *(float4*)&Xl[row][c4] = l;
        }
        // stage W_s (64 x 64), split
        #pragma unroll
        for (int j = 0; j < 4; j++) {
            int idx = t + 256 * j;       // float4 index, 1024 total
            int kr = idx >> 4, c4 = (idx & 15) * 4;
            float4 v = *(const float4*)(Wl + s * 4096 + kr * 64 + c4);
            float4 h, l;
            h.x = tf32_hi(v.x); l.x = v.x - h.x;
            h.y = tf32_hi(v.y); l.y = v.y - h.y;
            h.z = tf32_hi(v.z); l.z = v.z - h.z;
            h.w = tf32_hi(v.w); l.w = v.w - h.w;
            *(float4*)&Wh[kr][c4]  = h;
            *(float4*)&Wlo[kr][c4] = l;
        }
        __syncthreads();

        #pragma unroll
        for (int kc = 0; kc < 8; kc++) {
            const int kr = kc * 8;
            uint32_t ah[4][4], al[4][4], bh[4][2], bl[4][2];
            #pragma unroll
            for (int im = 0; im < 4; im++) {
                const int rb = wr * 64 + im * 16 + g;
                ah[im][0] = __float_as_uint(Xh[rb    ][kr + tg]);
                ah[im][1] = __float_as_uint(Xh[rb + 8][kr + tg]);
                ah[im][2] = __float_as_uint(Xh[rb    ][kr + tg + 4]);
                ah[im][3] = __float_as_uint(Xh[rb + 8][kr + tg + 4]);
                al[im][0] = __float_as_uint(Xl[rb    ][kr + tg]);
                al[im][1] = __float_as_uint(Xl[rb + 8][kr + tg]);
                al[im][2] = __float_as_uint(Xl[rb    ][kr + tg + 4]);
                al[im][3] = __float_as_uint(Xl[rb + 8][kr + tg + 4]);
            }
            #pragma unroll
            for (int in = 0; in < 4; in++) {
                const int cb = wc * 32 + in * 8 + g;
                bh[in][0] = __float_as_uint(Wh[kr + tg    ][cb]);
                bh[in][1] = __float_as_uint(Wh[kr + tg + 4][cb]);
                bl[in][0] = __float_as_uint(Wlo[kr + tg    ][cb]);
                bl[in][1] = __float_as_uint(Wlo[kr + tg + 4][cb]);
            }
            #pragma unroll
            for (int im = 0; im < 4; im++)
                #pragma unroll
                for (int in = 0; in < 4; in++) {
                    mma_tf32(c[im][in], ah[im], bh[in]);
                    mma_tf32(c[im][in], al[im], bh[in]);
                    mma_tf32(c[im][in], ah[im], bl[in]);
                }
        }
    }

    #pragma unroll
    for (int im = 0; im < 4; im++) {
        const long row = r0 + wr * 64 + im * 16 + g;
        #pragma unroll
        for (int in = 0; in < 4; in++) {
            const int col = wc * 32 + in * 8 + 2 * tg;
            *(float2*)(T + row * 64 + col)       = make_float2(c[im][in][0], c[im][in][1]);
            *(float2*)(T + (row + 8) * 64 + col) = make_float2(c[im][in][2], c[im][in][3]);
        }
    }
}

// -------- slim epilogue: h = Sn @ T[n] + bias_sum ; LN(m,d) ; ReLU -> X ------
__global__ __launch_bounds__(256)
void layer_epilogue(const float* __restrict__ T,
                    const float* __restrict__ Sn,       // (64,64)
                    const float* __restrict__ bconv_l,  // (4,64)
                    const float* __restrict__ gamma_l,  // (64,64)
                    const float* __restrict__ beta_l,   // (64,64)
                    float* __restrict__ Xout) {
    __shared__ float Ts[64][68];
    __shared__ float Sns[64][68];
    __shared__ float red[8];
    __shared__ float s_mu, s_rstd;

    const int n = blockIdx.x;
    const int t = threadIdx.x;
    const int u = t >> 2;
    const int q = t & 3;
    const long base = (long)n * FDIM;

    #pragma unroll
    for (int i = 0; i < 16; i++) {
        int idx = t + i * 256;
        Ts[idx >> 6][idx & 63]  = T[base + idx];
        Sns[idx >> 6][idx & 63] = Sn[idx];
    }
    __syncthreads();

    unsigned long long h2[4][2];
    #pragma unroll
    for (int v = 0; v < 4; v++)
        #pragma unroll
        for (int jj = 0; jj < 2; jj++) {
            int c = q * 4 + 16 * v + 2 * jj;
            float b0 = bconv_l[c]       + bconv_l[64 + c]
                     + bconv_l[128 + c] + bconv_l[192 + c];
            float b1 = bconv_l[c + 1]     + bconv_l[64 + c + 1]
                     + bconv_l[128 + c + 1] + bconv_l[192 + c + 1];
            h2[v][jj] = pack2f(b0, b1);
        }
    #pragma unroll 8
    for (int k = 0; k < 64; k++) {
        unsigned long long sv = pack2(Sns[u][k]);
        #pragma unroll
        for (int v = 0; v < 4; v++) {
            ulonglong2 w = *(const ulonglong2*)&Ts[k][q * 4 + 16 * v];
            fma2(h2[v][0], sv, w.x);
            fma2(h2[v][1], sv, w.y);
        }
    }

    float h[16];
    #pragma unroll
    for (int v = 0; v < 4; v++) {
        float2 a0 = unpack2(h2[v][0]);
        float2 a1 = unpack2(h2[v][1]);
        h[4 * v + 0] = a0.x; h[4 * v + 1] = a0.y;
        h[4 * v + 2] = a1.x; h[4 * v + 3] = a1.y;
    }

    const int lane = t & 31, wid = t >> 5;
    float lsum = 0.0f;
    #pragma unroll
    for (int j = 0; j < 16; j++) lsum += h[j];
    #pragma unroll
    for (int o = 16; o > 0; o >>= 1) lsum += __shfl_xor_sync(0xffffffffu, lsum, o);
    if (lane == 0) red[wid] = lsum;
    __syncthreads();
    if (t == 0) {
        float s = 0.0f;
        #pragma unroll
        for (int i = 0; i < 8; i++) s += red[i];
        s_mu = s * (1.0f / 4096.0f);
    }
    __syncthreads();
    const float mu = s_mu;

    float lv = 0.0f;
    #pragma unroll
    for (int j = 0; j < 16; j++) { float d = h[j] - mu; lv += d * d; }
    #pragma unroll
    for (int o = 16; o > 0; o >>= 1) lv += __shfl_xor_sync(0xffffffffu, lv, o);
    if (lane == 0) red[wid] = lv;
    __syncthreads();
    if (t == 0) {
        float s = 0.0f;
        #pragma unroll
        for (int i = 0; i < 8; i++) s += red[i];
        s_rstd = rsqrtf(s * (1.0f / 4096.0f) + LN_EPS);
    }
    __syncthreads();
    const float rstd = s_rstd;

    #pragma unroll
    for (int v = 0; v < 4; v++) {
        const int c = q * 4 + 16 * v;
        const float4 g4 = *(const float4*)(gamma_l + u * 64 + c);
        const float4 b4 = *(const float4*)(beta_l  + u * 64 + c);
        float4 o;
        o.x = fmaxf((h[4 * v + 0] - mu) * rstd * g4.x + b4.x, 0.0f);
        o.y = fmaxf((h[4 * v + 1] - mu) * rstd * g4.y + b4.y, 0.0f);
        o.z = fmaxf((h[4 * v + 2] - mu) * rstd * g4.z + b4.z, 0.0f);
        o.w = fmaxf((h[4 * v + 3] - mu) * rstd * g4.w + b4.w, 0.0f);
        *(float4*)(Xout + base + u * 64 + c) = o;
    }
}

// ----------- readout: out(2048,64) = X(2048,4096) @ Wl(4096,64) + bl --------
__global__ __launch_bounds__(256)
void final_gemm(const float* __restrict__ X, const float* __restrict__ Wl,
                const float* __restrict__ bl, float* __restrict__ out) {
    __shared__ float Xs[16][128];
    __shared__ float Ws[128][68];
    const int t = threadIdx.x;
    const long m0 = (long)blockIdx.x * 16;
    const int r  = t >> 4;
    const int cq = (t & 15) * 4;

    float acc[4] = {0.f, 0.f, 0.f, 0.f};

    for (int k0 = 0; k0 < FDIM; k0 += 128) {
        #pragma unroll
        for (int i = 0; i < 2; i++) {
            int idx = t + i * 256;
            int rr = idx >> 5, cc = (idx & 31) * 4;
            *(float4*)&Xs[rr][cc] = *(const float4*)(X + (m0 + rr) * FDIM + k0 + cc);
        }
        #pragma unroll
        for (int i = 0; i < 8; i++) {
            int idx = t + i * 256;
            int kk = idx >> 4, cc = (idx & 15) * 4;
            float4 v = *(const float4*)(Wl + (long)(k0 + kk) * 64 + cc);
            Ws[kk][cc] = v.x; Ws[kk][cc + 1] = v.y; Ws[kk][cc + 2] = v.z; Ws[kk][cc + 3] = v.w;
        }
        __syncthreads();
        #pragma unroll 16
        for (int kk = 0; kk < 128; kk++) {
            float xv = Xs[r][kk];
            #pragma unroll
            for (int j = 0; j < 4; j++) acc[j] += xv * Ws[kk][cq + j];
        }
        __syncthreads();
    }
    float4 v = make_float4(acc[0] + bl[cq], acc[1] + bl[cq + 1],
                           acc[2] + bl[cq + 2], acc[3] + bl[cq + 3]);
    *(float4*)(out + (m0 + r) * 64 + cq) = v;
}

// ---------------------------------------------------------------------------
extern "C" void kernel_launch(void* const* d_in, const int* in_sizes, int n_in,
                              void* d_out, int out_size) {
    const float* x_in    = (const float*)d_in[0];   // (2048,64,64)
    const int*   sub_adj = (const int*)  d_in[1];   // (64,64)
    const int*   adj     = (const int*)  d_in[2];   // (2048,2048)
    const float* W_convs = (const float*)d_in[3];   // (3,4,64,64)
    const float* b_convs = (const float*)d_in[4];   // (3,4,64)
    const float* ln_g    = (const float*)d_in[5];   // (3,64,64)
    const float* ln_b    = (const float*)d_in[6];   // (3,64,64)
    const float* W_lin   = (const float*)d_in[7];   // (4096,64)
    const float* b_lin   = (const float*)d_in[8];   // (64)
    float* out = (float*)d_out;

    float *Af, *AT, *A2, *A3, *X, *B1, *B2, *B3, *T, *Sn;
    cudaGetSymbolAddress((void**)&Af, g_Af);
    cudaGetSymbolAddress((void**)&AT, g_AT);
    cudaGetSymbolAddress((void**)&A2, g_A2);
    cudaGetSymbolAddress((void**)&A3, g_A3);
    cudaGetSymbolAddress((void**)&X,  g_X);
    cudaGetSymbolAddress((void**)&B1, g_B1);
    cudaGetSymbolAddress((void**)&B2, g_B2);
    cudaGetSymbolAddress((void**)&B3, g_B3);
    cudaGetSymbolAddress((void**)&T,  g_T);
    cudaGetSymbolAddress((void**)&Sn, g_Sn);

    cudaFuncSetAttribute(gemm_tt, cudaFuncAttributeMaxDynamicSharedMemorySize,
                         GEMM_SMEM);
    cudaFuncSetAttribute(wsum, cudaFuncAttributeMaxDynamicSharedMemorySize,
                         WSU_SMEM);

    // precompute: Af, AfT, (A^2)^T, (A^3)^T (all exact integer GEMMs), Sn
    cast_i2f<<<(NN * NN) / 256, 256>>>(adj, Af);
    cast_i2f_T<<<dim3(NN / 32, NN / 32), dim3(32, 8)>>>(adj, AT);
    gemm_tt<<<dim3(NN / TBN, NN / TBM), 256, GEMM_SMEM>>>(Af, AT, A2, NN, NN, NN);
    gemm_tt<<<dim3(NN / TBN, NN / TBM), 256, GEMM_SMEM>>>(Af, A2, A3, NN, NN, NN);
    compute_sn<<<1, 256>>>(sub_adj, Sn);

    const dim3 gmeta(FDIM / TBN, NN / TBM);   // (32, 8)
    for (int l = 0; l < 3; l++) {
        const float* curX = (l == 0) ? x_in : X;
        const float* Wl = W_convs + (long)l * 4 * 4096;

        // x1 = A @ x ; x2 = A^2 @ x1 ; x3 = A^3 @ x2
        gemm_tt<<<gmeta, 256, GEMM_SMEM>>>(AT, curX, B1, NN, FDIM, NN);
        gemm_tt<<<gmeta, 256, GEMM_SMEM>>>(A2, B1,  B2, NN, FDIM, NN);
        gemm_tt<<<gmeta, 256, GEMM_SMEM>>>(A3, B2,  B3, NN, FDIM, NN);

        // T = sum_i xi @ Wi (tensor, split-tf32 ~fp32 accurate)
        wsum<<<(NN * MDIM) / 256, 256, WSU_SMEM>>>(curX, B1, B2, B3, Wl, T);

        // X = relu(LN(Sn @ T + sum_i b_i))
        layer_epilogue<<<NN, 256>>>(T, Sn,
                                    b_convs + (long)l * 256,
                                    ln_g + (long)l * 4096,
                                    ln_b + (long)l * 4096,
                                    X);
    }

    final_gemm<<<NN / 16, 256>>>(X, W_lin, b_lin, out);
}

// round 13
// speedup vs baseline: 3.9130x; 1.0493x over previous
#include <cuda_runtime.h>
#include <cstdint>

// Problem constants
#define NN    2048          // meta nodes
#define MDIM  64            // subgraph nodes
#define DDIM  64            // channels
#define FDIM  4096          // MDIM*DDIM
#define OUTD  64
#define LN_EPS 1e-5f

// ------------------------- scratch (device globals; no allocation) ----------
__device__ float g_Af[NN * NN];     // A (row-major)
__device__ float g_AT[NN * NN];     // A^T
__device__ float g_A2[NN * NN];     // (A^2)^T
__device__ float g_A3[NN * NN];     // (A^3)^T
__device__ float g_X [NN * FDIM];
__device__ float g_B1[NN * FDIM];
__device__ float g_B2[NN * FDIM];
__device__ float g_B3[NN * FDIM];
__device__ float g_T [NN * FDIM];   // T = sum_i xi @ Wi
__device__ float g_Sn[MDIM * MDIM];

// ------------------------- int32 -> float cast ------------------------------
__global__ void cast_i2f(const int* __restrict__ a, float* __restrict__ o) {
    int i = blockIdx.x * blockDim.x + threadIdx.x;
    o[i] = (float)a[i];
}

// transpose-cast: oT[j,i] = (float)a[i,j], 32x32 smem tiles
__global__ void cast_i2f_T(const int* __restrict__ a, float* __restrict__ oT) {
    __shared__ float tile[32][33];
    int bx = blockIdx.x * 32, by = blockIdx.y * 32;
    int tx = threadIdx.x, ty = threadIdx.y;            // 32x8
    #pragma unroll
    for (int j = 0; j < 32; j += 8)
        tile[ty + j][tx] = (float)a[(long)(by + ty + j) * NN + bx + tx];
    __syncthreads();
    #pragma unroll
    for (int j = 0; j < 32; j += 8)
        oT[(long)(bx + ty + j) * NN + by + tx] = tile[tx][ty + j];
}

// ------------------------- Sn = D^-1/2 (S+I) D^-1/2 (256 threads) -----------
__global__ void compute_sn(const int* __restrict__ sub_adj, float* __restrict__ Sn) {
    __shared__ float part[MDIM][4];
    __shared__ float dinv[MDIM];
    const int t = threadIdx.x;           // 256
    const int u = t >> 2, q = t & 3;
    float s = 0.0f;
    #pragma unroll
    for (int v = 0; v < 16; v++) s += (float)sub_adj[u * MDIM + q * 16 + v];
    part[u][q] = s;
    __syncthreads();
    if (q == 0)
        dinv[u] = rsqrtf(1.0f + part[u][0] + part[u][1] + part[u][2] + part[u][3]);
    __syncthreads();
    #pragma unroll
    for (int j = 0; j < 16; j++) {
        int idx = t + j * 256;           // 0..4095
        int uu = idx >> 6, vv = idx & 63;
        float a = (float)sub_adj[idx] + (uu == vv ? 1.0f : 0.0f);
        Sn[idx] = dinv[uu] * a * dinv[vv];
    }
}

// ------------------------- mma / cp.async / f32x2 helpers --------------------
__device__ __forceinline__ void mma_tf32(float c[4], const uint32_t a[4],
                                         const uint32_t b[2]) {
    asm volatile(
        "mma.sync.aligned.m16n8k8.row.col.f32.tf32.tf32.f32 "
        "{%0,%1,%2,%3}, {%4,%5,%6,%7}, {%8,%9}, {%0,%1,%2,%3};\n"
        : "+f"(c[0]), "+f"(c[1]), "+f"(c[2]), "+f"(c[3])
        : "r"(a[0]), "r"(a[1]), "r"(a[2]), "r"(a[3]), "r"(b[0]), "r"(b[1]));
}

__device__ __forceinline__ void cp16(float* smem, const float* gmem) {
    uint32_t s = (uint32_t)__cvta_generic_to_shared(smem);
    asm volatile("cp.async.cg.shared.global [%0], [%1], 16;\n" :: "r"(s), "l"(gmem));
}
__device__ __forceinline__ void cp_commit() {
    asm volatile("cp.async.commit_group;\n");
}
template<int W> __device__ __forceinline__ void cp_wait() {
    asm volatile("cp.async.wait_group %0;\n" :: "n"(W));
}

__device__ __forceinline__ unsigned long long pack2(float x) {
    unsigned long long r;
    asm("mov.b64 %0, {%1, %1};" : "=l"(r) : "f"(x));
    return r;
}
__device__ __forceinline__ unsigned long long pack2f(float lo, float hi) {
    unsigned long long r;
    asm("mov.b64 %0, {%1, %2};" : "=l"(r) : "f"(lo), "f"(hi));
    return r;
}
__device__ __forceinline__ void fma2(unsigned long long& d, unsigned long long a,
                                     unsigned long long b) {
    asm("fma.rn.f32x2 %0, %1, %2, %0;" : "+l"(d) : "l"(a), "l"(b));
}
__device__ __forceinline__ float2 unpack2(unsigned long long v) {
    float2 f;
    asm("mov.b64 {%0, %1}, %2;" : "=f"(f.x), "=f"(f.y) : "l"(v));
    return f;
}

// ---------------- tensor-core GEMM: C(MxN) = (AT)^T (MxK) * B(KxN) ----------
// (unchanged) CTA 256x128x32, 256 threads, warp tile 64x64, 4 stages.
#define TBM 256
#define TBN 128
#define TBK 32
#define STAGES 4
#define ASPAD 264
#define BSPAD 136
#define GEMM_SMEM (STAGES * TBK * (ASPAD + BSPAD) * 4)   // 204800 bytes

__global__ __launch_bounds__(256, 1)
void gemm_tt(const float* __restrict__ AT, const float* __restrict__ B,
             float* __restrict__ C, int M, int N, int K) {
    extern __shared__ float sm[];
    float (*As)[TBK][ASPAD] = (float (*)[TBK][ASPAD])sm;
    float (*Bs)[TBK][BSPAD] = (float (*)[TBK][BSPAD])(sm + STAGES * TBK * ASPAD);

    const int t  = threadIdx.x;               // 0..255
    const long bm = (long)blockIdx.y * TBM;
    const long bn = (long)blockIdx.x * TBN;
    const int lane = t & 31;
    const int g  = lane >> 2;                 // 0..7
    const int tg = lane & 3;                  // 0..3
    const int w  = t >> 5;                    // 0..7
    const int wm = (w >> 1) * 64;             // 0,64,128,192
    const int wn = (w & 1) * 64;              // 0 or 64

    const int akk = t >> 3;
    const int ac0 = (t & 7) * 4;
    const int asw = ((akk >> 4) & 1) << 4;
    const float* Ag = AT + (long)akk * M + bm;
    const int bkk = t >> 5;
    const int bn4 = (t & 31) * 4;
    const float* Bg = B + (long)bkk * N + bn + bn4;

    float c[4][8][4];
    #pragma unroll
    for (int im = 0; im < 4; im++)
        #pragma unroll
        for (int in = 0; in < 8; in++) {
            c[im][in][0] = 0.f; c[im][in][1] = 0.f;
            c[im][in][2] = 0.f; c[im][in][3] = 0.f;
        }

    const int ktiles = K / TBK;

    #pragma unroll
    for (int s = 0; s < STAGES - 1; s++) {
        const long k0 = (long)s * TBK;
        #pragma unroll
        for (int j = 0; j < 8; j++)
            cp16(&As[s][akk][(ac0 + 32 * j) ^ asw], Ag + k0 * M + ac0 + 32 * j);
        #pragma unroll
        for (int j = 0; j < 4; j++)
            cp16(&Bs[s][bkk + 8 * j][bn4], Bg + (k0 + 8 * j) * N);
        cp_commit();
    }

    for (int i = 0; i < ktiles; i++) {
        if (i + STAGES - 1 < ktiles) cp_wait<STAGES - 2>(); else cp_wait<0>();
        __syncthreads();

        const int nx = i + STAGES - 1;
        if (nx < ktiles) {
            const int st = nx & (STAGES - 1);
            const long k0 = (long)nx * TBK;
            #pragma unroll
            for (int j = 0; j < 8; j++)
                cp16(&As[st][akk][(ac0 + 32 * j) ^ asw], Ag + k0 * M + ac0 + 32 * j);
            #pragma unroll
            for (int j = 0; j < 4; j++)
                cp16(&Bs[st][bkk + 8 * j][bn4], Bg + (k0 + 8 * j) * N);
            cp_commit();
        }

        const int cur = i & (STAGES - 1);
        #pragma unroll
        for (int ks = 0; ks < 4; ks++) {
            const int kr = ks * 8;
            const int sw = (ks >> 1) << 4;
            uint32_t af[4][4], bf[8][2];
            #pragma unroll
            for (int im = 0; im < 4; im++) {
                const int m0 = (wm + im * 16 + g) ^ sw;
                const int m8 = (wm + im * 16 + g + 8) ^ sw;
                af[im][0] = __float_as_uint(As[cur][kr + tg    ][m0]);
                af[im][1] = __float_as_uint(As[cur][kr + tg    ][m8]);
                af[im][2] = __float_as_uint(As[cur][kr + tg + 4][m0]);
                af[im][3] = __float_as_uint(As[cur][kr + tg + 4][m8]);
            }
            #pragma unroll
            for (int in = 0; in < 8; in++) {
                const int nb = wn + in * 8 + g;
                bf[in][0] = __float_as_uint(Bs[cur][kr + tg    ][nb]);
                bf[in][1] = __float_as_uint(Bs[cur][kr + tg + 4][nb]);
            }
            #pragma unroll
            for (int im = 0; im < 4; im++)
                #pragma unroll
                for (int in = 0; in < 8; in++)
                    mma_tf32(c[im][in], af[im], bf[in]);
        }
    }

    #pragma unroll
    for (int im = 0; im < 4; im++) {
        const long row = bm + wm + im * 16 + g;
        #pragma unroll
        for (int in = 0; in < 8; in++) {
            const int col = bn + wn + in * 8 + 2 * tg;
            float* Cp = C + row * N + col;
            *(float2*)Cp           = make_float2(c[im][in][0], c[im][in][1]);
            *(float2*)(Cp + 8 * N) = make_float2(c[im][in][2], c[im][in][3]);
        }
    }
}

// ============ wsum: T(131072x64) = sum_i Xi(131072x64) @ Wi(64x64) ===========
// Tensor-core, single-pass tf32 (raw-bit truncation; ~1e-4 rel — inputs
// already carry tf32-level noise from the propagation GEMMs).
// CTA: 256 rows x 64 cols, 256 threads (8 warps, 4x2), warp tile 64x32.
// Pad 68 => all fragment LDS conflict-free. 87KB smem, 2 CTAs/SM.
#define WSU_XT (256 * 68)
#define WSU_WT (64 * 68)
#define WSU_SMEM ((WSU_XT + WSU_WT) * 4)   // 87040 bytes

__global__ __launch_bounds__(256, 2)
void wsum(const float* __restrict__ x0, const float* __restrict__ x1,
          const float* __restrict__ x2, const float* __restrict__ x3,
          const float* __restrict__ Wl,   // (4,64,64)
          float* __restrict__ T) {
    extern __shared__ float wsm[];
    float (*Xs)[68] = (float (*)[68])(wsm);
    float (*Ws)[68] = (float (*)[68])(wsm + WSU_XT);

    const int t = threadIdx.x;
    const long r0 = (long)blockIdx.x * 256;
    const int lane = t & 31;
    const int g  = lane >> 2;        // 0..7
    const int tg = lane & 3;         // 0..3
    const int w  = t >> 5;
    const int wr = w >> 1;           // 0..3 : 64-row group
    const int wc = w & 1;            // 0..1 : 32-col group

    float c[4][4][4];
    #pragma unroll
    for (int im = 0; im < 4; im++)
        #pragma unroll
        for (int in = 0; in < 4; in++) {
            c[im][in][0] = 0.f; c[im][in][1] = 0.f;
            c[im][in][2] = 0.f; c[im][in][3] = 0.f;
        }

    const float* xs[4] = { x0, x1, x2, x3 };

    #pragma unroll
    for (int s = 0; s < 4; s++) {
        __syncthreads();                 // smem reuse guard
        // stage X (256 rows x 64), raw fp32 bits
        #pragma unroll
        for (int j = 0; j < 16; j++) {
            int idx = t + 256 * j;       // float4 index, 4096 total
            int row = idx >> 4, c4 = (idx & 15) * 4;
            *(float4*)&Xs[row][c4] =
                *(const float4*)(xs[s] + (r0 + row) * 64 + c4);
        }
        // stage W_s (64 x 64)
        #pragma unroll
        for (int j = 0; j < 4; j++) {
            int idx = t + 256 * j;       // float4 index, 1024 total
            int kr = idx >> 4, c4 = (idx & 15) * 4;
            *(float4*)&Ws[kr][c4] =
                *(const float4*)(Wl + s * 4096 + kr * 64 + c4);
        }
        __syncthreads();

        #pragma unroll
        for (int kc = 0; kc < 8; kc++) {
            const int kr = kc * 8;
            uint32_t ah[4][4], bh[4][2];
            #pragma unroll
            for (int im = 0; im < 4; im++) {
                const int rb = wr * 64 + im * 16 + g;
                ah[im][0] = __float_as_uint(Xs[rb    ][kr + tg]);
                ah[im][1] = __float_as_uint(Xs[rb + 8][kr + tg]);
                ah[im][2] = __float_as_uint(Xs[rb    ][kr + tg + 4]);
                ah[im][3] = __float_as_uint(Xs[rb + 8][kr + tg + 4]);
            }
            #pragma unroll
            for (int in = 0; in < 4; in++) {
                const int cb = wc * 32 + in * 8 + g;
                bh[in][0] = __float_as_uint(Ws[kr + tg    ][cb]);
                bh[in][1] = __float_as_uint(Ws[kr + tg + 4][cb]);
            }
            #pragma unroll
            for (int im = 0; im < 4; im++)
                #pragma unroll
                for (int in = 0; in < 4; in++)
                    mma_tf32(c[im][in], ah[im], bh[in]);
        }
    }

    #pragma unroll
    for (int im = 0; im < 4; im++) {
        const long row = r0 + wr * 64 + im * 16 + g;
        #pragma unroll
        for (int in = 0; in < 4; in++) {
            const int col = wc * 32 + in * 8 + 2 * tg;
            *(float2*)(T + row * 64 + col)       = make_float2(c[im][in][0], c[im][in][1]);
            *(float2*)(T + (row + 8) * 64 + col) = make_float2(c[im][in][2], c[im][in][3]);
        }
    }
}

// -------- slim epilogue: h = Sn @ T[n] + bias_sum ; LN(m,d) ; ReLU -> X ------
__global__ __launch_bounds__(256)
void layer_epilogue(const float* __restrict__ T,
                    const float* __restrict__ Sn,       // (64,64)
                    const float* __restrict__ bconv_l,  // (4,64)
                    const float* __restrict__ gamma_l,  // (64,64)
                    const float* __restrict__ beta_l,   // (64,64)
                    float* __restrict__ Xout) {
    __shared__ float Ts[64][68];
    __shared__ float Sns[64][68];
    __shared__ float red[8];
    __shared__ float s_mu, s_rstd;

    const int n = blockIdx.x;
    const int t = threadIdx.x;
    const int u = t >> 2;
    const int q = t & 3;
    const long base = (long)n * FDIM;

    #pragma unroll
    for (int i = 0; i < 16; i++) {
        int idx = t + i * 256;
        Ts[idx >> 6][idx & 63]  = T[base + idx];
        Sns[idx >> 6][idx & 63] = Sn[idx];
    }
    __syncthreads();

    unsigned long long h2[4][2];
    #pragma unroll
    for (int v = 0; v < 4; v++)
        #pragma unroll
        for (int jj = 0; jj < 2; jj++) {
            int c = q * 4 + 16 * v + 2 * jj;
            float b0 = bconv_l[c]       + bconv_l[64 + c]
                     + bconv_l[128 + c] + bconv_l[192 + c];
            float b1 = bconv_l[c + 1]     + bconv_l[64 + c + 1]
                     + bconv_l[128 + c + 1] + bconv_l[192 + c + 1];
            h2[v][jj] = pack2f(b0, b1);
        }
    #pragma unroll 8
    for (int k = 0; k < 64; k++) {
        unsigned long long sv = pack2(Sns[u][k]);
        #pragma unroll
        for (int v = 0; v < 4; v++) {
            ulonglong2 w = *(const ulonglong2*)&Ts[k][q * 4 + 16 * v];
            fma2(h2[v][0], sv, w.x);
            fma2(h2[v][1], sv, w.y);
        }
    }

    float h[16];
    #pragma unroll
    for (int v = 0; v < 4; v++) {
        float2 a0 = unpack2(h2[v][0]);
        float2 a1 = unpack2(h2[v][1]);
        h[4 * v + 0] = a0.x; h[4 * v + 1] = a0.y;
        h[4 * v + 2] = a1.x; h[4 * v + 3] = a1.y;
    }

    const int lane = t & 31, wid = t >> 5;
    float lsum = 0.0f;
    #pragma unroll
    for (int j = 0; j < 16; j++) lsum += h[j];
    #pragma unroll
    for (int o = 16; o > 0; o >>= 1) lsum += __shfl_xor_sync(0xffffffffu, lsum, o);
    if (lane == 0) red[wid] = lsum;
    __syncthreads();
    if (t == 0) {
        float s = 0.0f;
        #pragma unroll
        for (int i = 0; i < 8; i++) s += red[i];
        s_mu = s * (1.0f / 4096.0f);
    }
    __syncthreads();
    const float mu = s_mu;

    float lv = 0.0f;
    #pragma unroll
    for (int j = 0; j < 16; j++) { float d = h[j] - mu; lv += d * d; }
    #pragma unroll
    for (int o = 16; o > 0; o >>= 1) lv += __shfl_xor_sync(0xffffffffu, lv, o);
    if (lane == 0) red[wid] = lv;
    __syncthreads();
    if (t == 0) {
        float s = 0.0f;
        #pragma unroll
        for (int i = 0; i < 8; i++) s += red[i];
        s_rstd = rsqrtf(s * (1.0f / 4096.0f) + LN_EPS);
    }
    __syncthreads();
    const float rstd = s_rstd;

    #pragma unroll
    for (int v = 0; v < 4; v++) {
        const int c = q * 4 + 16 * v;
        const float4 g4 = *(const float4*)(gamma_l + u * 64 + c);
        const float4 b4 = *(const float4*)(beta_l  + u * 64 + c);
        float4 o;
        o.x = fmaxf((h[4 * v + 0] - mu) * rstd * g4.x + b4.x, 0.0f);
        o.y = fmaxf((h[4 * v + 1] - mu) * rstd * g4.y + b4.y, 0.0f);
        o.z = fmaxf((h[4 * v + 2] - mu) * rstd * g4.z + b4.z, 0.0f);
        o.w = fmaxf((h[4 * v + 3] - mu) * rstd * g4.w + b4.w, 0.0f);
        *(float4*)(Xout + base + u * 64 + c) = o;
    }
}

// ----------- readout: out(2048,64) = X(2048,4096) @ Wl(4096,64) + bl --------
__global__ __launch_bounds__(256)
void final_gemm(const float* __restrict__ X, const float* __restrict__ Wl,
                const float* __restrict__ bl, float* __restrict__ out) {
    __shared__ float Xs[16][128];
    __shared__ float Ws[128][68];
    const int t = threadIdx.x;
    const long m0 = (long)blockIdx.x * 16;
    const int r  = t >> 4;
    const int cq = (t & 15) * 4;

    float acc[4] = {0.f, 0.f, 0.f, 0.f};

    for (int k0 = 0; k0 < FDIM; k0 += 128) {
        #pragma unroll
        for (int i = 0; i < 2; i++) {
            int idx = t + i * 256;
            int rr = idx >> 5, cc = (idx & 31) * 4;
            *(float4*)&Xs[rr][cc] = *(const float4*)(X + (m0 + rr) * FDIM + k0 + cc);
        }
        #pragma unroll
        for (int i = 0; i < 8; i++) {
            int idx = t + i * 256;
            int kk = idx >> 4, cc = (idx & 15) * 4;
            float4 v = *(const float4*)(Wl + (long)(k0 + kk) * 64 + cc);
            Ws[kk][cc] = v.x; Ws[kk][cc + 1] = v.y; Ws[kk][cc + 2] = v.z; Ws[kk][cc + 3] = v.w;
        }
        __syncthreads();
        #pragma unroll 16
        for (int kk = 0; kk < 128; kk++) {
            float xv = Xs[r][kk];
            #pragma unroll
            for (int j = 0; j < 4; j++) acc[j] += xv * Ws[kk][cq + j];
        }
        __syncthreads();
    }
    float4 v = make_float4(acc[0] + bl[cq], acc[1] + bl[cq + 1],
                           acc[2] + bl[cq + 2], acc[3] + bl[cq + 3]);
    *(float4*)(out + (m0 + r) * 64 + cq) = v;
}

// ---------------------------------------------------------------------------
extern "C" void kernel_launch(void* const* d_in, const int* in_sizes, int n_in,
                              void* d_out, int out_size) {
    const float* x_in    = (const float*)d_in[0];   // (2048,64,64)
    const int*   sub_adj = (const int*)  d_in[1];   // (64,64)
    const int*   adj     = (const int*)  d_in[2];   // (2048,2048)
    const float* W_convs = (const float*)d_in[3];   // (3,4,64,64)
    const float* b_convs = (const float*)d_in[4];   // (3,4,64)
    const float* ln_g    = (const float*)d_in[5];   // (3,64,64)
    const float* ln_b    = (const float*)d_in[6];   // (3,64,64)
    const float* W_lin   = (const float*)d_in[7];   // (4096,64)
    const float* b_lin   = (const float*)d_in[8];   // (64)
    float* out = (float*)d_out;

    float *Af, *AT, *A2, *A3, *X, *B1, *B2, *B3, *T, *Sn;
    cudaGetSymbolAddress((void**)&Af, g_Af);
    cudaGetSymbolAddress((void**)&AT, g_AT);
    cudaGetSymbolAddress((void**)&A2, g_A2);
    cudaGetSymbolAddress((void**)&A3, g_A3);
    cudaGetSymbolAddress((void**)&X,  g_X);
    cudaGetSymbolAddress((void**)&B1, g_B1);
    cudaGetSymbolAddress((void**)&B2, g_B2);
    cudaGetSymbolAddress((void**)&B3, g_B3);
    cudaGetSymbolAddress((void**)&T,  g_T);
    cudaGetSymbolAddress((void**)&Sn, g_Sn);

    cudaFuncSetAttribute(gemm_tt, cudaFuncAttributeMaxDynamicSharedMemorySize,
                         GEMM_SMEM);
    cudaFuncSetAttribute(wsum, cudaFuncAttributeMaxDynamicSharedMemorySize,
                         WSU_SMEM);

    // precompute: Af, AfT, (A^2)^T, (A^3)^T (all exact integer GEMMs), Sn
    cast_i2f<<<(NN * NN) / 256, 256>>>(adj, Af);
    cast_i2f_T<<<dim3(NN / 32, NN / 32), dim3(32, 8)>>>(adj, AT);
    gemm_tt<<<dim3(NN / TBN, NN / TBM), 256, GEMM_SMEM>>>(Af, AT, A2, NN, NN, NN);
    gemm_tt<<<dim3(NN / TBN, NN / TBM), 256, GEMM_SMEM>>>(Af, A2, A3, NN, NN, NN);
    compute_sn<<<1, 256>>>(sub_adj, Sn);

    const dim3 gmeta(FDIM / TBN, NN / TBM);   // (32, 8)
    for (int l = 0; l < 3; l++) {
        const float* curX = (l == 0) ? x_in : X;
        const float* Wl = W_convs + (long)l * 4 * 4096;

        // x1 = A @ x ; x2 = A^2 @ x1 ; x3 = A^3 @ x2
        gemm_tt<<<gmeta, 256, GEMM_SMEM>>>(AT, curX, B1, NN, FDIM, NN);
        gemm_tt<<<gmeta, 256, GEMM_SMEM>>>(A2, B1,  B2, NN, FDIM, NN);
        gemm_tt<<<gmeta, 256, GEMM_SMEM>>>(A3, B2,  B3, NN, FDIM, NN);

        // T = sum_i xi @ Wi (tensor, single-pass tf32)
        wsum<<<(NN * MDIM) / 256, 256, WSU_SMEM>>>(curX, B1, B2, B3, Wl, T);

        // X = relu(LN(Sn @ T + sum_i b_i))
        layer_epilogue<<<NN, 256>>>(T, Sn,
                                    b_convs + (long)l * 256,
                                    ln_g + (long)l * 4096,
                                    ln_b + (long)l * 4096,
                                    X);
    }

    final_gemm<<<NN / 16, 256>>>(X, W_lin, b_lin, out);
}